// round 1
// baseline (speedup 1.0000x reference)
#include <cuda_runtime.h>

#define BSZ   8192
#define DDIM  1024
#define NODES 4096
#define GRIDW 64

// d2 <= 4956  <=>  sqrt(d2) <= 70.4000025 (radius), exact for integer d2
#define D2_MAX 4956

// ---------------- scratch (__device__ globals: no allocation) ----------------
__device__ unsigned long long g_bmu[BSZ];      // packed (ordered dist bits << 32) | node
__device__ float g_Y[NODES * DDIM];            // scatter-accumulated x per BMU cell (16 MB)
__device__ float g_cnt[NODES];                 // BMU histogram
__device__ float g_m2[NODES];                  // ||map_w[n]||^2
__device__ float g_cs[NODES];                  // sum_p cnt[p] * L0[p,n]  (alpha excluded)

__device__ __forceinline__ float neg_inv_2r2() {
    const float r = 70.4f + 1e-6f;             // SIGMA*decrease + EPS, decrease = 1 at count=0
    return -1.0f / (2.0f * r * r);
}

// ---------------- K0: init (zero Y/cnt, reset bmu, compute m2) ----------------
__global__ void k_init(const float* __restrict__ mw) {
    int tid = threadIdx.x, bid = blockIdx.x;
    int gidx = bid * 256 + tid;                       // 4096*256 = 1,048,576 = NODES*DDIM/4
    ((float4*)g_Y)[gidx] = make_float4(0.f, 0.f, 0.f, 0.f);
    if (gidx < BSZ)   g_bmu[gidx] = 0xFFFFFFFFFFFFFFFFull;
    if (gidx < NODES) g_cnt[gidx] = 0.f;

    // m2 for node = bid (1024 floats, 256 threads -> 1 float4 each)
    float4 v = ((const float4*)(mw + (size_t)bid * DDIM))[tid];
    float s = v.x * v.x + v.y * v.y + v.z * v.z + v.w * v.w;
    #pragma unroll
    for (int o = 16; o; o >>= 1) s += __shfl_down_sync(0xFFFFFFFFu, s, o);
    __shared__ float ws[8];
    if ((tid & 31) == 0) ws[tid >> 5] = s;
    __syncthreads();
    if (tid == 0) {
        float t = 0.f;
        #pragma unroll
        for (int i = 0; i < 8; i++) t += ws[i];
        g_m2[bid] = t;
    }
}

// ---------------- K1: fused SGEMM (x @ map^T) + per-row argmin ----------------
// argmin_n (x2 + m2[n] - 2 dot)  ==  argmin_n (m2[n] - 2 dot)   (x2 constant per row)
__global__ __launch_bounds__(256) void k_dist_argmin(const float* __restrict__ x,
                                                     const float* __restrict__ mw) {
    __shared__ float As[16][132];   // x tile, k-major
    __shared__ float Bs[16][132];   // map tile, k-major
    __shared__ float m2s[128];
    __shared__ unsigned long long rowmin[128];

    int tid = threadIdx.x;
    int n0 = blockIdx.x * 128;      // node tile (32 tiles)
    int b0 = blockIdx.y * 128;      // sample tile (64 tiles)
    int tx = tid & 15, ty = tid >> 4;

    if (tid < 128) { m2s[tid] = g_m2[n0 + tid]; rowmin[tid] = 0xFFFFFFFFFFFFFFFFull; }

    float acc[8][8];
    #pragma unroll
    for (int i = 0; i < 8; i++)
        #pragma unroll
        for (int j = 0; j < 8; j++) acc[i][j] = 0.f;

    for (int k0 = 0; k0 < DDIM; k0 += 16) {
        #pragma unroll
        for (int l = 0; l < 2; l++) {
            int idx = tid + l * 256;              // 0..511
            int r  = idx >> 2;                    // 0..127
            int kc = (idx & 3) << 2;              // 0,4,8,12
            float4 av = *(const float4*)(x  + (size_t)(b0 + r) * DDIM + k0 + kc);
            As[kc + 0][r] = av.x; As[kc + 1][r] = av.y; As[kc + 2][r] = av.z; As[kc + 3][r] = av.w;
            float4 bv = *(const float4*)(mw + (size_t)(n0 + r) * DDIM + k0 + kc);
            Bs[kc + 0][r] = bv.x; Bs[kc + 1][r] = bv.y; Bs[kc + 2][r] = bv.z; Bs[kc + 3][r] = bv.w;
        }
        __syncthreads();
        #pragma unroll
        for (int kk = 0; kk < 16; kk++) {
            float a[8], bb[8];
            *(float4*)(a)      = *(const float4*)&As[kk][ty * 8];
            *(float4*)(a + 4)  = *(const float4*)&As[kk][ty * 8 + 4];
            *(float4*)(bb)     = *(const float4*)&Bs[kk][tx * 8];
            *(float4*)(bb + 4) = *(const float4*)&Bs[kk][tx * 8 + 4];
            #pragma unroll
            for (int i = 0; i < 8; i++)
                #pragma unroll
                for (int j = 0; j < 8; j++) acc[i][j] += a[i] * bb[j];
        }
        __syncthreads();
    }

    // epilogue: packed argmin (ties -> lowest node index, matches jnp.argmin)
    #pragma unroll
    for (int i = 0; i < 8; i++) {
        int rrow = ty * 8 + i;
        unsigned long long best = 0xFFFFFFFFFFFFFFFFull;
        #pragma unroll
        for (int j = 0; j < 8; j++) {
            int nl = tx * 8 + j;
            float v = m2s[nl] - 2.0f * acc[i][j];
            unsigned u = __float_as_uint(v);
            u = (u & 0x80000000u) ? ~u : (u | 0x80000000u);
            unsigned long long key = ((unsigned long long)u << 32) | (unsigned)(n0 + nl);
            best = key < best ? key : best;
        }
        atomicMin(&rowmin[rrow], best);
    }
    __syncthreads();
    if (tid < 128) atomicMin(&g_bmu[b0 + tid], rowmin[tid]);
}

// ---------------- K2: scatter x rows into Y by BMU cell + histogram ----------------
__global__ void k_scatter(const float* __restrict__ x) {
    int b = blockIdx.x;
    int p = (int)(g_bmu[b] & 0xFFFFFFFFull);
    if (threadIdx.x == 0) atomicAdd(&g_cnt[p], 1.0f);
    const float* xr = x + (size_t)b * DDIM;
    float* yr = g_Y + (size_t)p * DDIM;
    for (int d = threadIdx.x; d < DDIM; d += blockDim.x)
        atomicAdd(&yr[d], xr[d]);
}

// ---------------- K3: cs[n] = sum_p cnt[p] * L0[p,n] ----------------
__global__ __launch_bounds__(256) void k_colsum() {
    __shared__ float cnts[NODES];   // 16 KB
    __shared__ float e[64];
    int tid = threadIdx.x;
    int n = blockIdx.x * 256 + tid;
    float c2 = neg_inv_2r2();
    for (int i = tid; i < 64; i += 256) e[i] = expf((float)(i * i) * c2);
    for (int i = tid; i < NODES; i += 256) cnts[i] = g_cnt[i];
    __syncthreads();
    int ni = n >> 6, nj = n & 63;
    float s = 0.f;
    for (int pi = 0; pi < GRIDW; pi++) {
        int di = pi - ni;
        int di2 = di * di;
        float ei = e[abs(di)];
        int base = pi * GRIDW;
        #pragma unroll 4
        for (int pj = 0; pj < GRIDW; pj++) {
            float c = cnts[base + pj];
            int dj = pj - nj;
            int d2 = di2 + dj * dj;
            if (d2 <= D2_MAX) s += c * ei * e[abs(dj)];
        }
    }
    g_cs[n] = s;
}

// ---------------- K4: U = L0^T @ Y, out = map + alpha/B * (U - cs*map) ----------------
__global__ __launch_bounds__(256) void k_update(const float* __restrict__ mw,
                                                float* __restrict__ out) {
    __shared__ float Ls[16][132];   // L0[p, n_local]
    __shared__ float Ys[16][132];   // Y[p, d_local]
    __shared__ float e[64];
    __shared__ float css[128];

    int tid = threadIdx.x;
    int d0 = blockIdx.x * 128;      // 8 tiles
    int n0 = blockIdx.y * 128;      // 32 tiles
    int tx = tid & 15, ty = tid >> 4;

    float c2 = neg_inv_2r2();
    if (tid < 64)  e[tid] = expf((float)(tid * tid) * c2);
    if (tid < 128) css[tid] = g_cs[n0 + tid];
    __syncthreads();

    float acc[8][8];
    #pragma unroll
    for (int i = 0; i < 8; i++)
        #pragma unroll
        for (int j = 0; j < 8; j++) acc[i][j] = 0.f;

    for (int p0 = 0; p0 < NODES; p0 += 16) {
        #pragma unroll
        for (int l = 0; l < 2; l++) {
            int idx = tid + l * 256;              // 0..511
            int pr = idx >> 5;                    // 0..15
            int c  = (idx & 31) << 2;             // 0..124
            *(float4*)&Ys[pr][c] = *(const float4*)(g_Y + (size_t)(p0 + pr) * DDIM + d0 + c);
        }
        {
            int pr  = ty;                         // tid*8/128
            int nl0 = tx * 8;
            int p = p0 + pr;
            int pi = p >> 6, pj = p & 63;
            #pragma unroll
            for (int l = 0; l < 8; l++) {
                int n = n0 + nl0 + l;
                int di = pi - (n >> 6), dj = pj - (n & 63);
                int d2 = di * di + dj * dj;
                Ls[pr][nl0 + l] = (d2 <= D2_MAX) ? e[abs(di)] * e[abs(dj)] : 0.f;
            }
        }
        __syncthreads();
        #pragma unroll
        for (int kk = 0; kk < 16; kk++) {
            float a[8], bb[8];
            *(float4*)(a)      = *(const float4*)&Ls[kk][ty * 8];
            *(float4*)(a + 4)  = *(const float4*)&Ls[kk][ty * 8 + 4];
            *(float4*)(bb)     = *(const float4*)&Ys[kk][tx * 8];
            *(float4*)(bb + 4) = *(const float4*)&Ys[kk][tx * 8 + 4];
            #pragma unroll
            for (int i = 0; i < 8; i++)
                #pragma unroll
                for (int j = 0; j < 8; j++) acc[i][j] += a[i] * bb[j];
        }
        __syncthreads();
    }

    const float scale = 0.5f / 8192.0f;           // ALPHA / B
    #pragma unroll
    for (int i = 0; i < 8; i++) {
        int n = n0 + ty * 8 + i;
        float cs = css[ty * 8 + i];
        #pragma unroll
        for (int j = 0; j < 8; j += 4) {
            size_t off = (size_t)n * DDIM + d0 + tx * 8 + j;
            float4 m = *(const float4*)(mw + off);
            float4 o;
            o.x = m.x + scale * (acc[i][j + 0] - cs * m.x);
            o.y = m.y + scale * (acc[i][j + 1] - cs * m.y);
            o.z = m.z + scale * (acc[i][j + 2] - cs * m.z);
            o.w = m.w + scale * (acc[i][j + 3] - cs * m.w);
            *(float4*)(out + off) = o;
        }
    }
}

// ---------------- launch ----------------
extern "C" void kernel_launch(void* const* d_in, const int* in_sizes, int n_in,
                              void* d_out, int out_size) {
    const float* x  = (const float*)d_in[0];
    const float* mw = (const float*)d_in[1];
    // d_in[2] = location_vects: row-major (i,j) meshgrid -> node n has (i=n/64, j=n%64); hardcoded.
    float* out = (float*)d_out;

    k_init<<<NODES, 256>>>(mw);
    dim3 g1(NODES / 128, BSZ / 128);
    k_dist_argmin<<<g1, 256>>>(x, mw);
    k_scatter<<<BSZ, 256>>>(x);
    k_colsum<<<NODES / 256, 256>>>();
    dim3 g4(DDIM / 128, NODES / 128);
    k_update<<<g4, 256>>>(mw, out);
}

// round 3
// speedup vs baseline: 1.6434x; 1.6434x over previous
#include <cuda_runtime.h>
#include <cstdint>

#define BSZ   8192
#define DDIM  1024
#define NODES 4096
#define GRIDW 64
#define D2_MAX 4956          // integer d2 <= 4956 <=> sqrt(d2) <= radius (exact)

// ---------------- scratch ----------------
__device__ unsigned long long g_bmu[BSZ];
__device__ float g_Y[NODES * DDIM];
__device__ float g_cnt[NODES];
__device__ float g_m2[NODES];
__device__ float g_cs[NODES];

__device__ __forceinline__ float neg_inv_2r2() {
    const float r = 70.4f + 1e-6f;
    return -1.0f / (2.0f * r * r);
}

static __device__ __forceinline__ uint32_t smem_u32(const void* p) {
    uint32_t a;
    asm("{ .reg .u64 t; cvta.to.shared.u64 t, %1; cvt.u32.u64 %0, t; }" : "=r"(a) : "l"(p));
    return a;
}
static __device__ __forceinline__ uint32_t f2tf(float v) {
    uint32_t r;
    asm("cvt.rna.tf32.f32 %0, %1;" : "=r"(r) : "f"(v));
    return r;
}
static __device__ __forceinline__ void split_tf(float v, uint32_t& h, uint32_t& l) {
    h = f2tf(v);
    l = f2tf(v - __uint_as_float(h));
}
static __device__ __forceinline__ void mma_tf32(float* c, const uint32_t* a, const uint32_t* b) {
    asm volatile(
        "mma.sync.aligned.m16n8k8.row.col.f32.tf32.tf32.f32 "
        "{%0,%1,%2,%3}, {%4,%5,%6,%7}, {%8,%9}, {%0,%1,%2,%3};"
        : "+f"(c[0]), "+f"(c[1]), "+f"(c[2]), "+f"(c[3])
        : "r"(a[0]), "r"(a[1]), "r"(a[2]), "r"(a[3]), "r"(b[0]), "r"(b[1]));
}
static __device__ __forceinline__ void cp16(uint32_t dst, const void* src) {
    asm volatile("cp.async.cg.shared.global [%0], [%1], 16;" :: "r"(dst), "l"(src));
}
#define CP_COMMIT() asm volatile("cp.async.commit_group;" ::: "memory")
#define CP_WAIT1()  asm volatile("cp.async.wait_group 1;" ::: "memory")

// ---------------- K0: init ----------------
__global__ void k_init(const float* __restrict__ mw) {
    int tid = threadIdx.x, bid = blockIdx.x;
    int gidx = bid * 256 + tid;
    ((float4*)g_Y)[gidx] = make_float4(0.f, 0.f, 0.f, 0.f);
    if (gidx < BSZ)   g_bmu[gidx] = 0xFFFFFFFFFFFFFFFFull;
    if (gidx < NODES) g_cnt[gidx] = 0.f;

    float4 v = ((const float4*)(mw + (size_t)bid * DDIM))[tid];
    float s = v.x * v.x + v.y * v.y + v.z * v.z + v.w * v.w;
    #pragma unroll
    for (int o = 16; o; o >>= 1) s += __shfl_down_sync(0xFFFFFFFFu, s, o);
    __shared__ float ws[8];
    if ((tid & 31) == 0) ws[tid >> 5] = s;
    __syncthreads();
    if (tid == 0) {
        float t = 0.f;
        #pragma unroll
        for (int i = 0; i < 8; i++) t += ws[i];
        g_m2[bid] = t;
    }
}

// ---------------- K1: 3xTF32 mma GEMM (x @ map^T) + argmin ----------------
// smem layout (floats): stage s in [0,3): A at s*5120 (128x20), B at s*5120+2560 (128x20)
// m2s at 15360 (128 floats), rowmin(u64) at byte 61952. total 62976 B.
#define K1_SMEM 62976
__global__ void __launch_bounds__(256) k1_dist_argmin(const float* __restrict__ x,
                                                      const float* __restrict__ mw) {
    extern __shared__ float sm[];
    float* m2s = sm + 15360;
    unsigned long long* rowmin = (unsigned long long*)(sm + 15488);
    uint32_t sbase = smem_u32(sm);

    int tid = threadIdx.x;
    int lane = tid & 31, wid = tid >> 5;
    int warpM = wid & 1, warpN = wid >> 1;      // 2 x 4 warps; warp tile 64m x 32n
    int gid = lane >> 2, tig = lane & 3;
    int n0 = blockIdx.x * 128, b0 = blockIdx.y * 128;

    if (tid < 128) { m2s[tid] = g_m2[n0 + tid]; rowmin[tid] = 0xFFFFFFFFFFFFFFFFull; }

    float acc[4][4][4];
    #pragma unroll
    for (int a = 0; a < 4; a++)
        #pragma unroll
        for (int b = 0; b < 4; b++)
            #pragma unroll
            for (int c = 0; c < 4; c++) acc[a][b][c] = 0.f;

    int ldrow = tid >> 2, ldc = (tid & 3) * 4;   // loader coords (512 chunks, 2/thread)
    auto load_tile = [&](int i) {
        int s = i % 3;
        int k0 = i * 16;
        #pragma unroll
        for (int u = 0; u < 2; u++) {
            int row = ldrow + u * 64;
            uint32_t dA = sbase + (uint32_t)(s * 20480 + row * 80 + ldc * 4);
            cp16(dA, x + (size_t)(b0 + row) * DDIM + k0 + ldc);
            cp16(dA + 10240, mw + (size_t)(n0 + row) * DDIM + k0 + ldc);
        }
    };

    load_tile(0); CP_COMMIT();
    load_tile(1); CP_COMMIT();

    for (int i = 0; i < 64; i++) {
        CP_WAIT1();
        __syncthreads();
        if (i + 2 < 64) load_tile(i + 2);
        CP_COMMIT();

        const float* Ab = sm + (i % 3) * 5120;
        const float* Bb = Ab + 2560;
        #pragma unroll
        for (int kk = 0; kk < 2; kk++) {
            int kb = kk * 8;
            uint32_t ah[4][4], al[4][4];
            #pragma unroll
            for (int mt = 0; mt < 4; mt++) {
                const float* p = Ab + (warpM * 64 + mt * 16 + gid) * 20 + kb + tig;
                split_tf(p[0],   ah[mt][0], al[mt][0]);
                split_tf(p[160], ah[mt][1], al[mt][1]);
                split_tf(p[4],   ah[mt][2], al[mt][2]);
                split_tf(p[164], ah[mt][3], al[mt][3]);
            }
            uint32_t bh[4][2], bl[4][2];
            #pragma unroll
            for (int nt = 0; nt < 4; nt++) {
                const float* p = Bb + (warpN * 32 + nt * 8 + gid) * 20 + kb + tig;
                split_tf(p[0], bh[nt][0], bl[nt][0]);
                split_tf(p[4], bh[nt][1], bl[nt][1]);
            }
            #pragma unroll
            for (int mt = 0; mt < 4; mt++)
                #pragma unroll
                for (int nt = 0; nt < 4; nt++) {
                    mma_tf32(acc[mt][nt], al[mt], bh[nt]);
                    mma_tf32(acc[mt][nt], ah[mt], bl[nt]);
                    mma_tf32(acc[mt][nt], ah[mt], bh[nt]);
                }
        }
    }

    // argmin epilogue
    #pragma unroll
    for (int mt = 0; mt < 4; mt++) {
        int rl = warpM * 64 + mt * 16 + gid;
        unsigned long long k0v = 0xFFFFFFFFFFFFFFFFull, k1v = k0v;
        #pragma unroll
        for (int nt = 0; nt < 4; nt++) {
            #pragma unroll
            for (int j = 0; j < 2; j++) {
                int cl = warpN * 32 + nt * 8 + tig * 2 + j;
                float v0 = m2s[cl] - 2.0f * acc[mt][nt][j];
                float v1 = m2s[cl] - 2.0f * acc[mt][nt][2 + j];
                unsigned u0 = __float_as_uint(v0);
                u0 = (u0 & 0x80000000u) ? ~u0 : (u0 | 0x80000000u);
                unsigned u1 = __float_as_uint(v1);
                u1 = (u1 & 0x80000000u) ? ~u1 : (u1 | 0x80000000u);
                unsigned long long key0 = ((unsigned long long)u0 << 32) | (unsigned)(n0 + cl);
                unsigned long long key1 = ((unsigned long long)u1 << 32) | (unsigned)(n0 + cl);
                k0v = key0 < k0v ? key0 : k0v;
                k1v = key1 < k1v ? key1 : k1v;
            }
        }
        #pragma unroll
        for (int o = 1; o <= 2; o <<= 1) {
            unsigned long long t0 = __shfl_xor_sync(0xFFFFFFFFu, k0v, o);
            unsigned long long t1 = __shfl_xor_sync(0xFFFFFFFFu, k1v, o);
            k0v = t0 < k0v ? t0 : k0v;
            k1v = t1 < k1v ? t1 : k1v;
        }
        if (tig == 0) {
            atomicMin(&rowmin[rl], k0v);
            atomicMin(&rowmin[rl + 8], k1v);
        }
    }
    __syncthreads();
    if (tid < 128) atomicMin(&g_bmu[b0 + tid], rowmin[tid]);
}

// ---------------- K2: scatter ----------------
__global__ void k_scatter(const float* __restrict__ x) {
    int b = blockIdx.x;
    int p = (int)(g_bmu[b] & 0xFFFFFFFFull);
    if (threadIdx.x == 0) atomicAdd(&g_cnt[p], 1.0f);
    const float* xr = x + (size_t)b * DDIM;
    float* yr = g_Y + (size_t)p * DDIM;
    for (int d = threadIdx.x; d < DDIM; d += blockDim.x)
        atomicAdd(&yr[d], xr[d]);
}

// ---------------- K3: cs[n] = sum_p cnt[p]*L0[p,n] ----------------
__global__ __launch_bounds__(256) void k_colsum() {
    __shared__ float cnts[NODES];
    __shared__ float e[64];
    int tid = threadIdx.x;
    float c2 = neg_inv_2r2();
    if (tid < 64) e[tid] = expf((float)(tid * tid) * c2);
    for (int i = tid; i < NODES; i += 256) cnts[i] = g_cnt[i];
    __syncthreads();
    int nl = tid >> 2, part = tid & 3;
    int n = blockIdx.x * 64 + nl;
    int ni = n >> 6, nj = n & 63;
    float s = 0.f;
    for (int pi = part; pi < GRIDW; pi += 4) {
        int di = pi - ni, di2 = di * di;
        float ei = e[abs(di)];
        int base = pi * GRIDW;
        #pragma unroll 4
        for (int pj = 0; pj < GRIDW; pj++) {
            int dj = pj - nj, d2 = di2 + dj * dj;
            if (d2 <= D2_MAX) s += cnts[base + pj] * ei * e[abs(dj)];
        }
    }
    s += __shfl_down_sync(0xFFFFFFFFu, s, 2);
    s += __shfl_down_sync(0xFFFFFFFFu, s, 1);
    if (part == 0) g_cs[n] = s;
}

// ---------------- K4: tf32 mma, U = L0^T @ Y; out = map + a/B*(U - cs*map) ----------------
__global__ void __launch_bounds__(256) k4_update(const float* __restrict__ mw,
                                                 float* __restrict__ out) {
    __shared__ float Ls[2][128][20];     // L tile [n_local][k=p_local], tf32-rounded
    __shared__ float Bs[3][16][132];     // Y tile [p_local][d_local]
    __shared__ float e[64];
    __shared__ float css[128];

    uint32_t bsb = smem_u32(Bs);
    int tid = threadIdx.x;
    int lane = tid & 31, wid = tid >> 5;
    int warpM = wid & 1, warpN = wid >> 1;
    int gid = lane >> 2, tig = lane & 3;
    int d0 = blockIdx.x * 128;           // 8 tiles
    int n0 = blockIdx.y * 128;           // 32 tiles

    float c2 = neg_inv_2r2();
    if (tid < 64)  e[tid] = expf((float)(tid * tid) * c2);
    if (tid < 128) css[tid] = g_cs[n0 + tid];

    float acc[4][4][4];
    #pragma unroll
    for (int a = 0; a < 4; a++)
        #pragma unroll
        for (int b = 0; b < 4; b++)
            #pragma unroll
            for (int c = 0; c < 4; c++) acc[a][b][c] = 0.f;

    int ldp = tid >> 5, ldc = (tid & 31) * 4;    // 512 chunks, 2/thread
    auto load_y = [&](int i) {
        int s = i % 3;
        int p0 = i * 16;
        #pragma unroll
        for (int u = 0; u < 2; u++) {
            int pr = ldp + u * 8;
            uint32_t dst = bsb + (uint32_t)(s * 8448 + pr * 528 + ldc * 4);
            cp16(dst, g_Y + (size_t)(p0 + pr) * DDIM + d0 + ldc);
        }
    };

    load_y(0); CP_COMMIT();
    load_y(1); CP_COMMIT();
    __syncthreads();                     // e/css ready

    int ni_s = 0;                        // just to keep compiler happy
    (void)ni_s;

    for (int i = 0; i < 256; i++) {
        // generate L tile for this iter into buffer i&1
        int buf = i & 1;
        int p0 = i * 16;
        #pragma unroll
        for (int t = 0; t < 8; t++) {
            int idx = tid + t * 256;
            int nl = idx >> 4, kl = idx & 15;
            int p = p0 + kl;
            int pi = p >> 6, pj = p & 63;
            int n = n0 + nl;
            int di = pi - (n >> 6), dj = pj - (n & 63);
            int d2 = di * di + dj * dj;
            float val = (d2 <= D2_MAX) ? e[abs(di)] * e[abs(dj)] : 0.f;
            Ls[buf][nl][kl] = __uint_as_float(f2tf(val));
        }
        CP_WAIT1();
        __syncthreads();
        if (i + 2 < 256) load_y(i + 2);
        CP_COMMIT();

        const float (*Bc)[132] = Bs[i % 3];
        #pragma unroll
        for (int kk = 0; kk < 2; kk++) {
            int kb = kk * 8;
            uint32_t av[4][4];
            #pragma unroll
            for (int mt = 0; mt < 4; mt++) {
                const float* p = &Ls[buf][warpM * 64 + mt * 16 + gid][kb + tig];
                av[mt][0] = __float_as_uint(p[0]);
                av[mt][1] = __float_as_uint(p[160]);
                av[mt][2] = __float_as_uint(p[4]);
                av[mt][3] = __float_as_uint(p[164]);
            }
            uint32_t bv[4][2];
            #pragma unroll
            for (int nt = 0; nt < 4; nt++) {
                int col = warpN * 32 + nt * 8 + gid;
                bv[nt][0] = f2tf(Bc[kb + tig][col]);
                bv[nt][1] = f2tf(Bc[kb + tig + 4][col]);
            }
            #pragma unroll
            for (int mt = 0; mt < 4; mt++)
                #pragma unroll
                for (int nt = 0; nt < 4; nt++)
                    mma_tf32(acc[mt][nt], av[mt], bv[nt]);
        }
    }

    const float scale = 0.5f / 8192.0f;
    #pragma unroll
    for (int mt = 0; mt < 4; mt++) {
        int nl = warpM * 64 + mt * 16 + gid;
        float cs0 = css[nl], cs1 = css[nl + 8];
        size_t r0 = (size_t)(n0 + nl) * DDIM;
        size_t r1 = (size_t)(n0 + nl + 8) * DDIM;
        #pragma unroll
        for (int nt = 0; nt < 4; nt++) {
            int d = d0 + warpN * 32 + nt * 8 + tig * 2;
            float2 m0 = *(const float2*)(mw + r0 + d);
            float2 m1 = *(const float2*)(mw + r1 + d);
            float2 o0, o1;
            o0.x = m0.x + scale * (acc[mt][nt][0] - cs0 * m0.x);
            o0.y = m0.y + scale * (acc[mt][nt][1] - cs0 * m0.y);
            o1.x = m1.x + scale * (acc[mt][nt][2] - cs1 * m1.x);
            o1.y = m1.y + scale * (acc[mt][nt][3] - cs1 * m1.y);
            *(float2*)(out + r0 + d) = o0;
            *(float2*)(out + r1 + d) = o1;
        }
    }
}

// ---------------- launch ----------------
extern "C" void kernel_launch(void* const* d_in, const int* in_sizes, int n_in,
                              void* d_out, int out_size) {
    const float* x  = (const float*)d_in[0];
    const float* mw = (const float*)d_in[1];
    float* out = (float*)d_out;

    cudaFuncSetAttribute(k1_dist_argmin, cudaFuncAttributeMaxDynamicSharedMemorySize, K1_SMEM);

    k_init<<<NODES, 256>>>(mw);
    dim3 g1(NODES / 128, BSZ / 128);                 // 32 x 64
    k1_dist_argmin<<<g1, 256, K1_SMEM>>>(x, mw);
    k_scatter<<<BSZ, 256>>>(x);
    k_colsum<<<64, 256>>>();
    dim3 g4(DDIM / 128, NODES / 128);                // 8 x 32
    k4_update<<<g4, 256>>>(mw, out);
}

// round 4
// speedup vs baseline: 1.8819x; 1.1451x over previous
#include <cuda_runtime.h>
#include <cstdint>

#define BSZ   8192
#define DDIM  1024
#define NODES 4096
#define GRIDW 64
#define D2_MAX 4956          // integer d2 <= 4956 <=> sqrt(d2) <= radius (exact)

// ---------------- scratch ----------------
__device__ unsigned long long g_bmu[BSZ];
__device__ float g_Y[NODES * DDIM];            // per-BMU-cell accumulated x (16 MB)
__device__ float g_T[NODES * DDIM];            // conv intermediate (16 MB)
__device__ float g_cnt[NODES];
__device__ float g_m2[NODES];
__device__ float g_cs[NODES];

__device__ __forceinline__ float neg_inv_2r2() {
    const float r = 70.4f + 1e-6f;
    return -1.0f / (2.0f * r * r);
}

static __device__ __forceinline__ uint32_t smem_u32(const void* p) {
    uint32_t a;
    asm("{ .reg .u64 t; cvta.to.shared.u64 t, %1; cvt.u32.u64 %0, t; }" : "=r"(a) : "l"(p));
    return a;
}
static __device__ __forceinline__ uint32_t f2tf(float v) {
    uint32_t r;
    asm("cvt.rna.tf32.f32 %0, %1;" : "=r"(r) : "f"(v));
    return r;
}
static __device__ __forceinline__ void split_tf(float v, uint32_t& h, uint32_t& l) {
    h = f2tf(v);
    l = f2tf(v - __uint_as_float(h));
}
static __device__ __forceinline__ void mma_tf32(float* c, const uint32_t* a, const uint32_t* b) {
    asm volatile(
        "mma.sync.aligned.m16n8k8.row.col.f32.tf32.tf32.f32 "
        "{%0,%1,%2,%3}, {%4,%5,%6,%7}, {%8,%9}, {%0,%1,%2,%3};"
        : "+f"(c[0]), "+f"(c[1]), "+f"(c[2]), "+f"(c[3])
        : "r"(a[0]), "r"(a[1]), "r"(a[2]), "r"(a[3]), "r"(b[0]), "r"(b[1]));
}
static __device__ __forceinline__ void cp16(uint32_t dst, const void* src) {
    asm volatile("cp.async.cg.shared.global [%0], [%1], 16;" :: "r"(dst), "l"(src));
}
#define CP_COMMIT() asm volatile("cp.async.commit_group;" ::: "memory")
#define CP_WAIT1()  asm volatile("cp.async.wait_group 1;" ::: "memory")

// ---------------- K0: init ----------------
__global__ void k_init(const float* __restrict__ mw) {
    int tid = threadIdx.x, bid = blockIdx.x;
    int gidx = bid * 256 + tid;
    ((float4*)g_Y)[gidx] = make_float4(0.f, 0.f, 0.f, 0.f);
    if (gidx < BSZ)   g_bmu[gidx] = 0xFFFFFFFFFFFFFFFFull;
    if (gidx < NODES) g_cnt[gidx] = 0.f;

    float4 v = ((const float4*)(mw + (size_t)bid * DDIM))[tid];
    float s = v.x * v.x + v.y * v.y + v.z * v.z + v.w * v.w;
    #pragma unroll
    for (int o = 16; o; o >>= 1) s += __shfl_down_sync(0xFFFFFFFFu, s, o);
    __shared__ float ws[8];
    if ((tid & 31) == 0) ws[tid >> 5] = s;
    __syncthreads();
    if (tid == 0) {
        float t = 0.f;
        #pragma unroll
        for (int i = 0; i < 8; i++) t += ws[i];
        g_m2[bid] = t;
    }
}

// ---------------- K1: 3xTF32 mma GEMM (x @ map^T) + argmin ----------------
#define K1_SMEM 62976
__global__ void __launch_bounds__(256) k1_dist_argmin(const float* __restrict__ x,
                                                      const float* __restrict__ mw) {
    extern __shared__ float sm[];
    float* m2s = sm + 15360;
    unsigned long long* rowmin = (unsigned long long*)(sm + 15488);
    uint32_t sbase = smem_u32(sm);

    int tid = threadIdx.x;
    int lane = tid & 31, wid = tid >> 5;
    int warpM = wid & 1, warpN = wid >> 1;
    int gid = lane >> 2, tig = lane & 3;
    int n0 = blockIdx.x * 128, b0 = blockIdx.y * 128;

    if (tid < 128) { m2s[tid] = g_m2[n0 + tid]; rowmin[tid] = 0xFFFFFFFFFFFFFFFFull; }

    float acc[4][4][4];
    #pragma unroll
    for (int a = 0; a < 4; a++)
        #pragma unroll
        for (int b = 0; b < 4; b++)
            #pragma unroll
            for (int c = 0; c < 4; c++) acc[a][b][c] = 0.f;

    int ldrow = tid >> 2, ldc = (tid & 3) * 4;
    auto load_tile = [&](int i) {
        int s = i % 3;
        int k0 = i * 16;
        #pragma unroll
        for (int u = 0; u < 2; u++) {
            int row = ldrow + u * 64;
            uint32_t dA = sbase + (uint32_t)(s * 20480 + row * 80 + ldc * 4);
            cp16(dA, x + (size_t)(b0 + row) * DDIM + k0 + ldc);
            cp16(dA + 10240, mw + (size_t)(n0 + row) * DDIM + k0 + ldc);
        }
    };

    load_tile(0); CP_COMMIT();
    load_tile(1); CP_COMMIT();

    for (int i = 0; i < 64; i++) {
        CP_WAIT1();
        __syncthreads();
        if (i + 2 < 64) load_tile(i + 2);
        CP_COMMIT();

        const float* Ab = sm + (i % 3) * 5120;
        const float* Bb = Ab + 2560;
        #pragma unroll
        for (int kk = 0; kk < 2; kk++) {
            int kb = kk * 8;
            uint32_t ah[4][4], al[4][4];
            #pragma unroll
            for (int mt = 0; mt < 4; mt++) {
                const float* p = Ab + (warpM * 64 + mt * 16 + gid) * 20 + kb + tig;
                split_tf(p[0],   ah[mt][0], al[mt][0]);
                split_tf(p[160], ah[mt][1], al[mt][1]);
                split_tf(p[4],   ah[mt][2], al[mt][2]);
                split_tf(p[164], ah[mt][3], al[mt][3]);
            }
            uint32_t bh[4][2], bl[4][2];
            #pragma unroll
            for (int nt = 0; nt < 4; nt++) {
                const float* p = Bb + (warpN * 32 + nt * 8 + gid) * 20 + kb + tig;
                split_tf(p[0], bh[nt][0], bl[nt][0]);
                split_tf(p[4], bh[nt][1], bl[nt][1]);
            }
            #pragma unroll
            for (int mt = 0; mt < 4; mt++)
                #pragma unroll
                for (int nt = 0; nt < 4; nt++) {
                    mma_tf32(acc[mt][nt], al[mt], bh[nt]);
                    mma_tf32(acc[mt][nt], ah[mt], bl[nt]);
                    mma_tf32(acc[mt][nt], ah[mt], bh[nt]);
                }
        }
    }

    #pragma unroll
    for (int mt = 0; mt < 4; mt++) {
        int rl = warpM * 64 + mt * 16 + gid;
        unsigned long long k0v = 0xFFFFFFFFFFFFFFFFull, k1v = k0v;
        #pragma unroll
        for (int nt = 0; nt < 4; nt++) {
            #pragma unroll
            for (int j = 0; j < 2; j++) {
                int cl = warpN * 32 + nt * 8 + tig * 2 + j;
                float v0 = m2s[cl] - 2.0f * acc[mt][nt][j];
                float v1 = m2s[cl] - 2.0f * acc[mt][nt][2 + j];
                unsigned u0 = __float_as_uint(v0);
                u0 = (u0 & 0x80000000u) ? ~u0 : (u0 | 0x80000000u);
                unsigned u1 = __float_as_uint(v1);
                u1 = (u1 & 0x80000000u) ? ~u1 : (u1 | 0x80000000u);
                unsigned long long key0 = ((unsigned long long)u0 << 32) | (unsigned)(n0 + cl);
                unsigned long long key1 = ((unsigned long long)u1 << 32) | (unsigned)(n0 + cl);
                k0v = key0 < k0v ? key0 : k0v;
                k1v = key1 < k1v ? key1 : k1v;
            }
        }
        #pragma unroll
        for (int o = 1; o <= 2; o <<= 1) {
            unsigned long long t0 = __shfl_xor_sync(0xFFFFFFFFu, k0v, o);
            unsigned long long t1 = __shfl_xor_sync(0xFFFFFFFFu, k1v, o);
            k0v = t0 < k0v ? t0 : k0v;
            k1v = t1 < k1v ? t1 : k1v;
        }
        if (tig == 0) {
            atomicMin(&rowmin[rl], k0v);
            atomicMin(&rowmin[rl + 8], k1v);
        }
    }
    __syncthreads();
    if (tid < 128) atomicMin(&g_bmu[b0 + tid], rowmin[tid]);
}

// ---------------- K2: scatter ----------------
__global__ void k_scatter(const float* __restrict__ x) {
    int b = blockIdx.x;
    int p = (int)(g_bmu[b] & 0xFFFFFFFFull);
    if (threadIdx.x == 0) atomicAdd(&g_cnt[p], 1.0f);
    const float* xr = x + (size_t)b * DDIM;
    float* yr = g_Y + (size_t)p * DDIM;
    for (int d = threadIdx.x; d < DDIM; d += blockDim.x)
        atomicAdd(&yr[d], xr[d]);
}

// ---------------- K3: cs[n] = sum_p cnt[p]*L0[p,n] (exact mask) ----------------
__global__ __launch_bounds__(256) void k_colsum() {
    __shared__ float cnts[NODES];
    __shared__ float e[64];
    int tid = threadIdx.x;
    float c2 = neg_inv_2r2();
    if (tid < 64) e[tid] = expf((float)(tid * tid) * c2);
    for (int i = tid; i < NODES; i += 256) cnts[i] = g_cnt[i];
    __syncthreads();
    int nl = tid >> 2, part = tid & 3;
    int n = blockIdx.x * 64 + nl;
    int ni = n >> 6, nj = n & 63;
    float s = 0.f;
    for (int pi = part; pi < GRIDW; pi += 4) {
        int di = pi - ni, di2 = di * di;
        float ei = e[abs(di)];
        int base = pi * GRIDW;
        #pragma unroll 4
        for (int pj = 0; pj < GRIDW; pj++) {
            int dj = pj - nj, d2 = di2 + dj * dj;
            if (d2 <= D2_MAX) s += cnts[base + pj] * ei * e[abs(dj)];
        }
    }
    s += __shfl_down_sync(0xFFFFFFFFu, s, 2);
    s += __shfl_down_sync(0xFFFFFFFFu, s, 1);
    if (part == 0) g_cs[n] = s;
}

// ---------------- K4a: T[pi,nj,d] = sum_pj e[|pj-nj|] * Y[pi,pj,d] ----------------
__global__ __launch_bounds__(256) void k_convA() {
    __shared__ float Ys[64][128];     // 32 KB
    __shared__ float e[64];
    int tid = threadIdx.x;
    int pi = blockIdx.y;
    int d0 = blockIdx.x * 128;
    float c2 = neg_inv_2r2();
    if (tid < 64) e[tid] = expf((float)(tid * tid) * c2);
    for (int i = tid; i < 2048; i += 256) {
        int row = i >> 5, c4 = (i & 31) * 4;
        *(float4*)&Ys[row][c4] = *(const float4*)(g_Y + ((size_t)pi * 64 + row) * DDIM + d0 + c4);
    }
    __syncthreads();
    int d4 = (tid & 31) * 4;
    int njb = tid >> 5;               // 0..7, constant per warp
    #pragma unroll
    for (int g = 0; g < 8; g++) {
        int nj = njb * 8 + g;
        float4 acc = make_float4(0.f, 0.f, 0.f, 0.f);
        #pragma unroll 8
        for (int pj = 0; pj < 64; pj++) {
            float w = e[abs(pj - nj)];
            float4 y = *(const float4*)&Ys[pj][d4];
            acc.x += w * y.x; acc.y += w * y.y; acc.z += w * y.z; acc.w += w * y.w;
        }
        *(float4*)(g_T + ((size_t)pi * 64 + nj) * DDIM + d0 + d4) = acc;
    }
}

// ---------------- K4b: U0[ni,nj,d] = sum_pi e[|pi-ni|]*T[pi,nj,d]; fused update ----------------
__global__ __launch_bounds__(256) void k_convB(const float* __restrict__ mw,
                                               float* __restrict__ out) {
    __shared__ float Ts[64][128];
    __shared__ float e[64];
    __shared__ float css[64];
    int tid = threadIdx.x;
    int nj = blockIdx.y;
    int d0 = blockIdx.x * 128;
    float c2 = neg_inv_2r2();
    if (tid < 64) { e[tid] = expf((float)(tid * tid) * c2); css[tid] = g_cs[tid * 64 + nj]; }
    for (int i = tid; i < 2048; i += 256) {
        int row = i >> 5, c4 = (i & 31) * 4;
        *(float4*)&Ts[row][c4] = *(const float4*)(g_T + ((size_t)row * 64 + nj) * DDIM + d0 + c4);
    }
    __syncthreads();
    const float scale = 0.5f / 8192.0f;
    int d4 = (tid & 31) * 4;
    int nib = tid >> 5;
    #pragma unroll
    for (int g = 0; g < 8; g++) {
        int ni = nib * 8 + g;
        float4 acc = make_float4(0.f, 0.f, 0.f, 0.f);
        #pragma unroll 8
        for (int pi = 0; pi < 64; pi++) {
            float w = e[abs(pi - ni)];
            float4 t = *(const float4*)&Ts[pi][d4];
            acc.x += w * t.x; acc.y += w * t.y; acc.z += w * t.z; acc.w += w * t.w;
        }
        float cs = css[ni];
        size_t off = ((size_t)ni * 64 + nj) * DDIM + d0 + d4;
        float4 m = *(const float4*)(mw + off);
        float4 o;
        o.x = m.x + scale * (acc.x - cs * m.x);
        o.y = m.y + scale * (acc.y - cs * m.y);
        o.z = m.z + scale * (acc.z - cs * m.z);
        o.w = m.w + scale * (acc.w - cs * m.w);
        *(float4*)(out + off) = o;
    }
}

// ---------------- K4c: subtract out-of-radius correction (corner nodes only) ----------------
__global__ __launch_bounds__(256) void k_corr(float* __restrict__ out) {
    int n = blockIdx.x;
    int ni = n >> 6, nj = n & 63;
    int u = max(ni, 63 - ni), v = max(nj, 63 - nj);
    if (u * u + v * v <= D2_MAX) return;     // no excluded pairs (uniform per block)
    __shared__ float e[64];
    int tid = threadIdx.x;
    float c2 = neg_inv_2r2();
    if (tid < 64) e[tid] = expf((float)(tid * tid) * c2);
    __syncthreads();
    int d4 = tid * 4;
    float4 acc = make_float4(0.f, 0.f, 0.f, 0.f);
    for (int pi = 0; pi < GRIDW; pi++) {
        int di = pi - ni;
        int rem = D2_MAX - di * di;          // always > 0 (di^2 <= 3969)
        int t = (int)sqrtf((float)rem);
        while (t * t > rem) --t;
        while ((t + 1) * (t + 1) <= rem) ++t;  // excluded: |pj-nj| >= t+1
        float ei = e[abs(di)];
        int hi1 = nj - t - 1;
        for (int pj = 0; pj <= hi1; pj++) {
            float w = ei * e[nj - pj];
            float4 y = *(const float4*)(g_Y + ((size_t)pi * 64 + pj) * DDIM + d4);
            acc.x += w * y.x; acc.y += w * y.y; acc.z += w * y.z; acc.w += w * y.w;
        }
        int lo2 = nj + t + 1;
        for (int pj = lo2; pj < GRIDW; pj++) {
            float w = ei * e[pj - nj];
            float4 y = *(const float4*)(g_Y + ((size_t)pi * 64 + pj) * DDIM + d4);
            acc.x += w * y.x; acc.y += w * y.y; acc.z += w * y.z; acc.w += w * y.w;
        }
    }
    const float scale = 0.5f / 8192.0f;
    size_t off = (size_t)n * DDIM + d4;
    float4 o = *(float4*)(out + off);
    o.x -= scale * acc.x; o.y -= scale * acc.y; o.z -= scale * acc.z; o.w -= scale * acc.w;
    *(float4*)(out + off) = o;
}

// ---------------- launch ----------------
extern "C" void kernel_launch(void* const* d_in, const int* in_sizes, int n_in,
                              void* d_out, int out_size) {
    const float* x  = (const float*)d_in[0];
    const float* mw = (const float*)d_in[1];
    float* out = (float*)d_out;

    cudaFuncSetAttribute(k1_dist_argmin, cudaFuncAttributeMaxDynamicSharedMemorySize, K1_SMEM);

    k_init<<<NODES, 256>>>(mw);
    dim3 g1(NODES / 128, BSZ / 128);
    k1_dist_argmin<<<g1, 256, K1_SMEM>>>(x, mw);
    k_scatter<<<BSZ, 256>>>(x);
    k_colsum<<<64, 256>>>();
    dim3 gc(DDIM / 128, GRIDW);                  // 8 x 64
    k_convA<<<gc, 256>>>();
    k_convB<<<gc, 256>>>(mw, out);
    k_corr<<<NODES, 256>>>(out);
}

// round 5
// speedup vs baseline: 2.7564x; 1.4647x over previous
#include <cuda_runtime.h>
#include <cuda_fp16.h>
#include <cstdint>

#define BSZ   8192
#define DDIM  1024
#define NODES 4096
#define GRIDW 64
#define D2_MAX 4956          // integer d2 <= 4956 <=> sqrt(d2) <= radius (exact)

// ---------------- scratch ----------------
__device__ unsigned long long g_bmu[BSZ];
__device__ float g_Y[NODES * DDIM];
__device__ float g_T[NODES * DDIM];
__device__ float g_cnt[NODES];
__device__ float g_m2[NODES];
__device__ float g_cs[NODES];
__device__ __half g_xh[BSZ * DDIM];      // 16 MB
__device__ __half g_xl[BSZ * DDIM];      // 16 MB
__device__ __half g_mh[NODES * DDIM];    // 8 MB
__device__ __half g_ml[NODES * DDIM];    // 8 MB

__device__ __forceinline__ float neg_inv_2r2() {
    const float r = 70.4f + 1e-6f;
    return -1.0f / (2.0f * r * r);
}
static __device__ __forceinline__ uint32_t smem_u32(const void* p) {
    uint32_t a;
    asm("{ .reg .u64 t; cvta.to.shared.u64 t, %1; cvt.u32.u64 %0, t; }" : "=r"(a) : "l"(p));
    return a;
}
static __device__ __forceinline__ void mma_f16(float* c, const uint32_t* a, const uint32_t* b) {
    asm volatile(
        "mma.sync.aligned.m16n8k16.row.col.f32.f16.f16.f32 "
        "{%0,%1,%2,%3}, {%4,%5,%6,%7}, {%8,%9}, {%0,%1,%2,%3};"
        : "+f"(c[0]), "+f"(c[1]), "+f"(c[2]), "+f"(c[3])
        : "r"(a[0]), "r"(a[1]), "r"(a[2]), "r"(a[3]), "r"(b[0]), "r"(b[1]));
}
static __device__ __forceinline__ void cp16(uint32_t dst, const void* src) {
    asm volatile("cp.async.cg.shared.global [%0], [%1], 16;" :: "r"(dst), "l"(src));
}
#define CP_COMMIT() asm volatile("cp.async.commit_group;" ::: "memory")
#define CP_WAIT1()  asm volatile("cp.async.wait_group 1;" ::: "memory")

static __device__ __forceinline__ int isqrt_le(int rem) {
    int t = (int)sqrtf((float)rem);
    while (t * t > rem) --t;
    while ((t + 1) * (t + 1) <= rem) ++t;
    return t;                                 // floor(sqrt(rem))
}

// ---------------- K0: init ----------------
__global__ void k_init(const float* __restrict__ mw) {
    int tid = threadIdx.x, bid = blockIdx.x;
    int gidx = bid * 256 + tid;
    ((float4*)g_Y)[gidx] = make_float4(0.f, 0.f, 0.f, 0.f);
    if (gidx < BSZ)   g_bmu[gidx] = 0xFFFFFFFFFFFFFFFFull;
    if (gidx < NODES) g_cnt[gidx] = 0.f;

    float4 v = ((const float4*)(mw + (size_t)bid * DDIM))[tid];
    float s = v.x * v.x + v.y * v.y + v.z * v.z + v.w * v.w;
    #pragma unroll
    for (int o = 16; o; o >>= 1) s += __shfl_down_sync(0xFFFFFFFFu, s, o);
    __shared__ float ws[8];
    if ((tid & 31) == 0) ws[tid >> 5] = s;
    __syncthreads();
    if (tid == 0) {
        float t = 0.f;
        #pragma unroll
        for (int i = 0; i < 8; i++) t += ws[i];
        g_m2[bid] = t;
    }
}

// ---------------- K0b: fp32 -> fp16 hi/lo split ----------------
__global__ void k_split(const float* __restrict__ x, const float* __restrict__ mw) {
    int r = blockIdx.x, tid = threadIdx.x;
    const float* src;
    __half *dh, *dl;
    if (r < BSZ) {
        src = x + (size_t)r * DDIM; dh = g_xh + (size_t)r * DDIM; dl = g_xl + (size_t)r * DDIM;
    } else {
        int m = r - BSZ;
        src = mw + (size_t)m * DDIM; dh = g_mh + (size_t)m * DDIM; dl = g_ml + (size_t)m * DDIM;
    }
    float4 v = ((const float4*)src)[tid];
    __half h0 = __float2half_rn(v.x), h1 = __float2half_rn(v.y);
    __half h2 = __float2half_rn(v.z), h3 = __float2half_rn(v.w);
    __half l0 = __float2half_rn(v.x - __half2float(h0));
    __half l1 = __float2half_rn(v.y - __half2float(h1));
    __half l2 = __float2half_rn(v.z - __half2float(h2));
    __half l3 = __float2half_rn(v.w - __half2float(h3));
    ((__half2*)dh)[tid * 2]     = __halves2half2(h0, h1);
    ((__half2*)dh)[tid * 2 + 1] = __halves2half2(h2, h3);
    ((__half2*)dl)[tid * 2]     = __halves2half2(l0, l1);
    ((__half2*)dl)[tid * 2 + 1] = __halves2half2(l2, l3);
}

// ---------------- K1: 3xFP16 mma GEMM (x @ map^T) + argmin ----------------
// smem (halves): stage s in [0,3): Ah s*20480, Al +5120, Bh +10240, Bl +15360
// row pitch 40 halves (80B). After 61440 halves: m2s (128 f32), rowmin (128 u64).
#define K1_PITCH 40
#define K1_HALVES (3 * 20480)
#define K1_SMEM (K1_HALVES * 2 + 512 + 1024)
__global__ void __launch_bounds__(256) k1_dist_argmin() {
    extern __shared__ __half sh[];
    float* m2s = (float*)(sh + K1_HALVES);
    unsigned long long* rowmin = (unsigned long long*)(sh + K1_HALVES + 256);
    uint32_t sbase = smem_u32(sh);

    int tid = threadIdx.x;
    int lane = tid & 31, wid = tid >> 5;
    int warpM = wid & 1, warpN = wid >> 1;      // warp tile 64m x 32n
    int gid = lane >> 2, tig = lane & 3;
    int n0 = blockIdx.x * 128, b0 = blockIdx.y * 128;

    if (tid < 128) { m2s[tid] = g_m2[n0 + tid]; rowmin[tid] = 0xFFFFFFFFFFFFFFFFull; }

    float acc[4][4][4];
    #pragma unroll
    for (int a = 0; a < 4; a++)
        #pragma unroll
        for (int b = 0; b < 4; b++)
            #pragma unroll
            for (int c = 0; c < 4; c++) acc[a][b][c] = 0.f;

    const __half* srcs[4] = { g_xh + (size_t)b0 * DDIM, g_xl + (size_t)b0 * DDIM,
                              g_mh + (size_t)n0 * DDIM, g_ml + (size_t)n0 * DDIM };

    auto load_tile = [&](int i) {
        int s = i % 3;
        int k0 = i * 32;
        #pragma unroll
        for (int arr = 0; arr < 4; arr++) {
            #pragma unroll
            for (int u = 0; u < 2; u++) {
                int ch = tid + u * 256;           // 0..511
                int row = ch >> 2, c = (ch & 3) * 8;
                const __half* g = srcs[arr] + (size_t)row * DDIM + k0 + c;
                uint32_t dst = sbase + 2u * (uint32_t)(s * 20480 + arr * 5120 + row * K1_PITCH + c);
                cp16(dst, g);
            }
        }
    };

    load_tile(0); CP_COMMIT();
    load_tile(1); CP_COMMIT();

    for (int i = 0; i < 32; i++) {
        CP_WAIT1();
        __syncthreads();
        if (i + 2 < 32) load_tile(i + 2);
        CP_COMMIT();

        const __half* Ah = sh + (i % 3) * 20480;
        const __half* Al = Ah + 5120;
        const __half* Bh = Ah + 10240;
        const __half* Bl = Ah + 15360;
        #pragma unroll
        for (int ks = 0; ks < 2; ks++) {
            int kb = ks * 16;
            uint32_t ah[4][4], al[4][4];
            #pragma unroll
            for (int mt = 0; mt < 4; mt++) {
                int off = (warpM * 64 + mt * 16 + gid) * K1_PITCH + kb + 2 * tig;
                ah[mt][0] = *(const uint32_t*)(Ah + off);
                ah[mt][1] = *(const uint32_t*)(Ah + off + 8 * K1_PITCH);
                ah[mt][2] = *(const uint32_t*)(Ah + off + 8);
                ah[mt][3] = *(const uint32_t*)(Ah + off + 8 * K1_PITCH + 8);
                al[mt][0] = *(const uint32_t*)(Al + off);
                al[mt][1] = *(const uint32_t*)(Al + off + 8 * K1_PITCH);
                al[mt][2] = *(const uint32_t*)(Al + off + 8);
                al[mt][3] = *(const uint32_t*)(Al + off + 8 * K1_PITCH + 8);
            }
            uint32_t bh[4][2], bl[4][2];
            #pragma unroll
            for (int nt = 0; nt < 4; nt++) {
                int off = (warpN * 32 + nt * 8 + gid) * K1_PITCH + kb + 2 * tig;
                bh[nt][0] = *(const uint32_t*)(Bh + off);
                bh[nt][1] = *(const uint32_t*)(Bh + off + 8);
                bl[nt][0] = *(const uint32_t*)(Bl + off);
                bl[nt][1] = *(const uint32_t*)(Bl + off + 8);
            }
            #pragma unroll
            for (int mt = 0; mt < 4; mt++)
                #pragma unroll
                for (int nt = 0; nt < 4; nt++) {
                    mma_f16(acc[mt][nt], ah[mt], bh[nt]);
                    mma_f16(acc[mt][nt], ah[mt], bl[nt]);
                    mma_f16(acc[mt][nt], al[mt], bh[nt]);
                }
        }
    }

    // argmin epilogue (acc frag layout: rows gid/gid+8, cols 2tig,2tig+1)
    #pragma unroll
    for (int mt = 0; mt < 4; mt++) {
        int rl = warpM * 64 + mt * 16 + gid;
        unsigned long long k0v = 0xFFFFFFFFFFFFFFFFull, k1v = k0v;
        #pragma unroll
        for (int nt = 0; nt < 4; nt++) {
            #pragma unroll
            for (int j = 0; j < 2; j++) {
                int cl = warpN * 32 + nt * 8 + tig * 2 + j;
                float v0 = m2s[cl] - 2.0f * acc[mt][nt][j];
                float v1 = m2s[cl] - 2.0f * acc[mt][nt][2 + j];
                unsigned u0 = __float_as_uint(v0);
                u0 = (u0 & 0x80000000u) ? ~u0 : (u0 | 0x80000000u);
                unsigned u1 = __float_as_uint(v1);
                u1 = (u1 & 0x80000000u) ? ~u1 : (u1 | 0x80000000u);
                unsigned long long key0 = ((unsigned long long)u0 << 32) | (unsigned)(n0 + cl);
                unsigned long long key1 = ((unsigned long long)u1 << 32) | (unsigned)(n0 + cl);
                k0v = key0 < k0v ? key0 : k0v;
                k1v = key1 < k1v ? key1 : k1v;
            }
        }
        #pragma unroll
        for (int o = 1; o <= 2; o <<= 1) {
            unsigned long long t0 = __shfl_xor_sync(0xFFFFFFFFu, k0v, o);
            unsigned long long t1 = __shfl_xor_sync(0xFFFFFFFFu, k1v, o);
            k0v = t0 < k0v ? t0 : k0v;
            k1v = t1 < k1v ? t1 : k1v;
        }
        if (tig == 0) {
            atomicMin(&rowmin[rl], k0v);
            atomicMin(&rowmin[rl + 8], k1v);
        }
    }
    __syncthreads();
    if (tid < 128) atomicMin(&g_bmu[b0 + tid], rowmin[tid]);
}

// ---------------- K2: scatter ----------------
__global__ void k_scatter(const float* __restrict__ x) {
    int b = blockIdx.x;
    int p = (int)(g_bmu[b] & 0xFFFFFFFFull);
    if (threadIdx.x == 0) atomicAdd(&g_cnt[p], 1.0f);
    const float* xr = x + (size_t)b * DDIM;
    float* yr = g_Y + (size_t)p * DDIM;
    for (int d = threadIdx.x; d < DDIM; d += blockDim.x)
        atomicAdd(&yr[d], xr[d]);
}

// ---------------- K3: cs[n] separable + exact corner correction ----------------
__global__ __launch_bounds__(256) void k_colsum() {
    __shared__ float cnts[NODES];
    __shared__ float e[64];
    __shared__ float T2[64][65];
    int tid = threadIdx.x;
    int ni = blockIdx.x;                      // one block per ni row
    float c2 = neg_inv_2r2();
    if (tid < 64) e[tid] = expf((float)(tid * tid) * c2);
    for (int i = tid; i < NODES; i += 256) cnts[i] = g_cnt[i];
    __syncthreads();
    for (int idx = tid; idx < 4096; idx += 256) {
        int pi = idx >> 6, nj = idx & 63;
        float s = 0.f;
        #pragma unroll 8
        for (int pj = 0; pj < 64; pj++) s += e[abs(pj - nj)] * cnts[pi * 64 + pj];
        T2[pi][nj] = s;
    }
    __syncthreads();
    int nj = tid >> 2, part = tid & 3;
    float s = 0.f;
    for (int pi = part; pi < GRIDW; pi += 4) {
        int di = pi - ni;
        float ei = e[abs(di)];
        s += ei * T2[pi][nj];
        int t = isqrt_le(D2_MAX - di * di);   // include |dj|<=t; subtract excluded
        for (int pj = 0; pj <= nj - t - 1; pj++) s -= ei * e[nj - pj] * cnts[pi * 64 + pj];
        for (int pj = nj + t + 1; pj < GRIDW; pj++) s -= ei * e[pj - nj] * cnts[pi * 64 + pj];
    }
    s += __shfl_down_sync(0xFFFFFFFFu, s, 2);
    s += __shfl_down_sync(0xFFFFFFFFu, s, 1);
    if (part == 0) g_cs[ni * 64 + nj] = s;
}

// ---------------- K4a: conv over pj ----------------
__global__ __launch_bounds__(256) void k_convA() {
    __shared__ float Ys[64][128];
    __shared__ float e[64];
    int tid = threadIdx.x;
    int pi = blockIdx.y;
    int d0 = blockIdx.x * 128;
    float c2 = neg_inv_2r2();
    if (tid < 64) e[tid] = expf((float)(tid * tid) * c2);
    for (int i = tid; i < 2048; i += 256) {
        int row = i >> 5, c4 = (i & 31) * 4;
        *(float4*)&Ys[row][c4] = *(const float4*)(g_Y + ((size_t)pi * 64 + row) * DDIM + d0 + c4);
    }
    __syncthreads();
    int d4 = (tid & 31) * 4;
    int njb = tid >> 5;
    #pragma unroll
    for (int g = 0; g < 8; g++) {
        int nj = njb * 8 + g;
        float4 acc = make_float4(0.f, 0.f, 0.f, 0.f);
        #pragma unroll 8
        for (int pj = 0; pj < 64; pj++) {
            float w = e[abs(pj - nj)];
            float4 y = *(const float4*)&Ys[pj][d4];
            acc.x += w * y.x; acc.y += w * y.y; acc.z += w * y.z; acc.w += w * y.w;
        }
        *(float4*)(g_T + ((size_t)pi * 64 + nj) * DDIM + d0 + d4) = acc;
    }
}

// ---------------- K4b: conv over pi + fused update ----------------
__global__ __launch_bounds__(256) void k_convB(const float* __restrict__ mw,
                                               float* __restrict__ out) {
    __shared__ float Ts[64][128];
    __shared__ float e[64];
    __shared__ float css[64];
    int tid = threadIdx.x;
    int nj = blockIdx.y;
    int d0 = blockIdx.x * 128;
    float c2 = neg_inv_2r2();
    if (tid < 64) { e[tid] = expf((float)(tid * tid) * c2); css[tid] = g_cs[tid * 64 + nj]; }
    for (int i = tid; i < 2048; i += 256) {
        int row = i >> 5, c4 = (i & 31) * 4;
        *(float4*)&Ts[row][c4] = *(const float4*)(g_T + ((size_t)row * 64 + nj) * DDIM + d0 + c4);
    }
    __syncthreads();
    const float scale = 0.5f / 8192.0f;
    int d4 = (tid & 31) * 4;
    int nib = tid >> 5;
    #pragma unroll
    for (int g = 0; g < 8; g++) {
        int ni = nib * 8 + g;
        float4 acc = make_float4(0.f, 0.f, 0.f, 0.f);
        #pragma unroll 8
        for (int pi = 0; pi < 64; pi++) {
            float w = e[abs(pi - ni)];
            float4 t = *(const float4*)&Ts[pi][d4];
            acc.x += w * t.x; acc.y += w * t.y; acc.z += w * t.z; acc.w += w * t.w;
        }
        float cs = css[ni];
        size_t off = ((size_t)ni * 64 + nj) * DDIM + d0 + d4;
        float4 m = *(const float4*)(mw + off);
        float4 o;
        o.x = m.x + scale * (acc.x - cs * m.x);
        o.y = m.y + scale * (acc.y - cs * m.y);
        o.z = m.z + scale * (acc.z - cs * m.z);
        o.w = m.w + scale * (acc.w - cs * m.w);
        *(float4*)(out + off) = o;
    }
}

// ---------------- K4c: out-of-radius correction (corner nodes only) ----------------
__global__ __launch_bounds__(256) void k_corr(float* __restrict__ out) {
    int n = blockIdx.x;
    int ni = n >> 6, nj = n & 63;
    int u = max(ni, 63 - ni), v = max(nj, 63 - nj);
    if (u * u + v * v <= D2_MAX) return;
    __shared__ float e[64];
    int tid = threadIdx.x;
    float c2 = neg_inv_2r2();
    if (tid < 64) e[tid] = expf((float)(tid * tid) * c2);
    __syncthreads();
    int d4 = tid * 4;
    float4 acc = make_float4(0.f, 0.f, 0.f, 0.f);
    for (int pi = 0; pi < GRIDW; pi++) {
        int di = pi - ni;
        int t = isqrt_le(D2_MAX - di * di);
        float ei = e[abs(di)];
        for (int pj = 0; pj <= nj - t - 1; pj++) {
            float w = ei * e[nj - pj];
            float4 y = *(const float4*)(g_Y + ((size_t)pi * 64 + pj) * DDIM + d4);
            acc.x += w * y.x; acc.y += w * y.y; acc.z += w * y.z; acc.w += w * y.w;
        }
        for (int pj = nj + t + 1; pj < GRIDW; pj++) {
            float w = ei * e[pj - nj];
            float4 y = *(const float4*)(g_Y + ((size_t)pi * 64 + pj) * DDIM + d4);
            acc.x += w * y.x; acc.y += w * y.y; acc.z += w * y.z; acc.w += w * y.w;
        }
    }
    const float scale = 0.5f / 8192.0f;
    size_t off = (size_t)n * DDIM + d4;
    float4 o = *(float4*)(out + off);
    o.x -= scale * acc.x; o.y -= scale * acc.y; o.z -= scale * acc.z; o.w -= scale * acc.w;
    *(float4*)(out + off) = o;
}

// ---------------- launch ----------------
extern "C" void kernel_launch(void* const* d_in, const int* in_sizes, int n_in,
                              void* d_out, int out_size) {
    const float* x  = (const float*)d_in[0];
    const float* mw = (const float*)d_in[1];
    float* out = (float*)d_out;

    cudaFuncSetAttribute(k1_dist_argmin, cudaFuncAttributeMaxDynamicSharedMemorySize, K1_SMEM);

    k_init<<<NODES, 256>>>(mw);
    k_split<<<BSZ + NODES, 256>>>(x, mw);
    dim3 g1(NODES / 128, BSZ / 128);
    k1_dist_argmin<<<g1, 256, K1_SMEM>>>();
    k_scatter<<<BSZ, 256>>>(x);
    k_colsum<<<GRIDW, 256>>>();
    dim3 gc(DDIM / 128, GRIDW);
    k_convA<<<gc, 256>>>();
    k_convB<<<gc, 256>>>(mw, out);
    k_corr<<<NODES, 256>>>(out);
}

// round 6
// speedup vs baseline: 2.9344x; 1.0646x over previous
#include <cuda_runtime.h>
#include <cuda_fp16.h>
#include <cstdint>

#define BSZ   8192
#define DDIM  1024
#define NODES 4096
#define GRIDW 64
#define D2_MAX 4956          // integer d2 <= 4956 <=> sqrt(d2) <= radius (exact)

// ---------------- scratch ----------------
__device__ unsigned long long g_bmu[BSZ];
__device__ float g_Y[NODES * DDIM];
__device__ float g_T[NODES * DDIM];
__device__ float g_cnt[NODES];
__device__ float g_m2[NODES];
__device__ float g_cs[NODES];
__device__ __half g_xh[BSZ * DDIM];
__device__ __half g_xl[BSZ * DDIM];
__device__ __half g_mh[NODES * DDIM];
__device__ __half g_ml[NODES * DDIM];

__device__ __forceinline__ float neg_inv_2r2() {
    const float r = 70.4f + 1e-6f;
    return -1.0f / (2.0f * r * r);
}
static __device__ __forceinline__ uint32_t smem_u32(const void* p) {
    uint32_t a;
    asm("{ .reg .u64 t; cvta.to.shared.u64 t, %1; cvt.u32.u64 %0, t; }" : "=r"(a) : "l"(p));
    return a;
}
static __device__ __forceinline__ void mma_f16(float* c, const uint32_t* a, const uint32_t* b) {
    asm volatile(
        "mma.sync.aligned.m16n8k16.row.col.f32.f16.f16.f32 "
        "{%0,%1,%2,%3}, {%4,%5,%6,%7}, {%8,%9}, {%0,%1,%2,%3};"
        : "+f"(c[0]), "+f"(c[1]), "+f"(c[2]), "+f"(c[3])
        : "r"(a[0]), "r"(a[1]), "r"(a[2]), "r"(a[3]), "r"(b[0]), "r"(b[1]));
}
static __device__ __forceinline__ void ldsm_x4(uint32_t* r, uint32_t addr) {
    asm volatile("ldmatrix.sync.aligned.m8n8.x4.shared.b16 {%0,%1,%2,%3}, [%4];"
                 : "=r"(r[0]), "=r"(r[1]), "=r"(r[2]), "=r"(r[3]) : "r"(addr));
}
static __device__ __forceinline__ void cp16(uint32_t dst, const void* src) {
    asm volatile("cp.async.cg.shared.global [%0], [%1], 16;" :: "r"(dst), "l"(src));
}
#define CP_COMMIT() asm volatile("cp.async.commit_group;" ::: "memory")
#define CP_WAIT1()  asm volatile("cp.async.wait_group 1;" ::: "memory")

static __device__ __forceinline__ int isqrt_le(int rem) {
    int t = (int)sqrtf((float)rem);
    while (t * t > rem) --t;
    while ((t + 1) * (t + 1) <= rem) ++t;
    return t;
}

// ---------------- K0: init ----------------
__global__ void k_init(const float* __restrict__ mw) {
    int tid = threadIdx.x, bid = blockIdx.x;
    int gidx = bid * 256 + tid;
    ((float4*)g_Y)[gidx] = make_float4(0.f, 0.f, 0.f, 0.f);
    if (gidx < BSZ)   g_bmu[gidx] = 0xFFFFFFFFFFFFFFFFull;
    if (gidx < NODES) g_cnt[gidx] = 0.f;

    float4 v = ((const float4*)(mw + (size_t)bid * DDIM))[tid];
    float s = v.x * v.x + v.y * v.y + v.z * v.z + v.w * v.w;
    #pragma unroll
    for (int o = 16; o; o >>= 1) s += __shfl_down_sync(0xFFFFFFFFu, s, o);
    __shared__ float ws[8];
    if ((tid & 31) == 0) ws[tid >> 5] = s;
    __syncthreads();
    if (tid == 0) {
        float t = 0.f;
        #pragma unroll
        for (int i = 0; i < 8; i++) t += ws[i];
        g_m2[bid] = t;
    }
}

// ---------------- K0b: fp32 -> fp16 hi/lo split ----------------
__global__ void k_split(const float* __restrict__ x, const float* __restrict__ mw) {
    int r = blockIdx.x, tid = threadIdx.x;
    const float* src;
    __half *dh, *dl;
    if (r < BSZ) {
        src = x + (size_t)r * DDIM; dh = g_xh + (size_t)r * DDIM; dl = g_xl + (size_t)r * DDIM;
    } else {
        int m = r - BSZ;
        src = mw + (size_t)m * DDIM; dh = g_mh + (size_t)m * DDIM; dl = g_ml + (size_t)m * DDIM;
    }
    float4 v = ((const float4*)src)[tid];
    __half h0 = __float2half_rn(v.x), h1 = __float2half_rn(v.y);
    __half h2 = __float2half_rn(v.z), h3 = __float2half_rn(v.w);
    __half l0 = __float2half_rn(v.x - __half2float(h0));
    __half l1 = __float2half_rn(v.y - __half2float(h1));
    __half l2 = __float2half_rn(v.z - __half2float(h2));
    __half l3 = __float2half_rn(v.w - __half2float(h3));
    ((__half2*)dh)[tid * 2]     = __halves2half2(h0, h1);
    ((__half2*)dh)[tid * 2 + 1] = __halves2half2(h2, h3);
    ((__half2*)dl)[tid * 2]     = __halves2half2(l0, l1);
    ((__half2*)dl)[tid * 2 + 1] = __halves2half2(l2, l3);
}

// ---------------- K1: 3xFP16 mma GEMM (x @ map^T) + argmin ----------------
// CTA tile 128m x 256n, 8 warps (2x4), warp tile 64x64, ldmatrix fragments.
// smem halves per stage (30720): Ah 0, Al 5120, Bh 10240, Bl 20480. pitch 40 halves.
#define K1_PITCH 40
#define K1_STAGE 30720
#define K1_HALVES (3 * K1_STAGE)
#define K1_SMEM (K1_HALVES * 2 + 1024 + 1024)
__global__ void __launch_bounds__(256, 1) k1_dist_argmin() {
    extern __shared__ __half sh[];
    float* m2s = (float*)(sh + K1_HALVES);
    unsigned long long* rowmin = (unsigned long long*)(sh + K1_HALVES + 512);
    uint32_t sbase = smem_u32(sh);

    int tid = threadIdx.x;
    int lane = tid & 31, wid = tid >> 5;
    int warpM = wid & 1, warpN = wid >> 1;      // warp tile 64m x 64n
    int gid = lane >> 2, tig = lane & 3;
    int lrow = lane & 15, lsel = (lane >> 4) * 8;
    int n0 = blockIdx.x * 256, b0 = blockIdx.y * 128;

    if (tid < 128) rowmin[tid] = 0xFFFFFFFFFFFFFFFFull;
    m2s[tid] = g_m2[n0 + tid];                  // 256 threads cover 256 nodes

    float acc[4][8][4];
    #pragma unroll
    for (int a = 0; a < 4; a++)
        #pragma unroll
        for (int b = 0; b < 8; b++)
            #pragma unroll
            for (int c = 0; c < 4; c++) acc[a][b][c] = 0.f;

    auto load_tile = [&](int i) {
        int s = i % 3;
        int k0 = i * 32;
        uint32_t stage = sbase + 2u * (uint32_t)(s * K1_STAGE);
        #pragma unroll
        for (int u = 0; u < 2; u++) {            // A: 512 chunks per array
            int ch = tid + u * 256;
            int row = ch >> 2, kc = (ch & 3) * 8;
            uint32_t d = stage + 2u * (uint32_t)(row * K1_PITCH + kc);
            size_t g = (size_t)(b0 + row) * DDIM + k0 + kc;
            cp16(d, g_xh + g);
            cp16(d + 2u * 5120u, g_xl + g);
        }
        #pragma unroll
        for (int u = 0; u < 4; u++) {            // B: 1024 chunks per array
            int ch = tid + u * 256;
            int row = ch >> 2, kc = (ch & 3) * 8;
            uint32_t d = stage + 2u * (uint32_t)(10240 + row * K1_PITCH + kc);
            size_t g = (size_t)(n0 + row) * DDIM + k0 + kc;
            cp16(d, g_mh + g);
            cp16(d + 2u * 10240u, g_ml + g);
        }
    };

    load_tile(0); CP_COMMIT();
    load_tile(1); CP_COMMIT();

    for (int i = 0; i < 32; i++) {
        CP_WAIT1();
        __syncthreads();
        if (i + 2 < 32) load_tile(i + 2);
        CP_COMMIT();

        uint32_t stage = sbase + 2u * (uint32_t)((i % 3) * K1_STAGE);
        #pragma unroll
        for (int ks = 0; ks < 2; ks++) {
            int kb = ks * 16;
            uint32_t ah[4][4], al[4][4];
            #pragma unroll
            for (int mt = 0; mt < 4; mt++) {
                uint32_t off = 2u * (uint32_t)((warpM * 64 + mt * 16 + lrow) * K1_PITCH + kb + lsel);
                ldsm_x4(ah[mt], stage + off);
                ldsm_x4(al[mt], stage + 2u * 5120u + off);
            }
            uint32_t bh[8][2], bl[8][2];
            #pragma unroll
            for (int pr = 0; pr < 4; pr++) {
                uint32_t off = 2u * (uint32_t)(10240 + (warpN * 64 + pr * 16 + lrow) * K1_PITCH + kb + lsel);
                uint32_t t[4];
                ldsm_x4(t, stage + off);
                bh[pr * 2][0] = t[0]; bh[pr * 2 + 1][0] = t[1];
                bh[pr * 2][1] = t[2]; bh[pr * 2 + 1][1] = t[3];
                ldsm_x4(t, stage + 2u * 10240u + off);
                bl[pr * 2][0] = t[0]; bl[pr * 2 + 1][0] = t[1];
                bl[pr * 2][1] = t[2]; bl[pr * 2 + 1][1] = t[3];
            }
            #pragma unroll
            for (int mt = 0; mt < 4; mt++)
                #pragma unroll
                for (int nt = 0; nt < 8; nt++) {
                    mma_f16(acc[mt][nt], ah[mt], bh[nt]);
                    mma_f16(acc[mt][nt], ah[mt], bl[nt]);
                    mma_f16(acc[mt][nt], al[mt], bh[nt]);
                }
        }
    }

    // argmin epilogue: acc rows gid/gid+8, cols 2tig, 2tig+1
    #pragma unroll
    for (int mt = 0; mt < 4; mt++) {
        int rl = warpM * 64 + mt * 16 + gid;
        unsigned long long k0v = 0xFFFFFFFFFFFFFFFFull, k1v = k0v;
        #pragma unroll
        for (int nt = 0; nt < 8; nt++) {
            #pragma unroll
            for (int j = 0; j < 2; j++) {
                int cl = warpN * 64 + nt * 8 + tig * 2 + j;
                float v0 = m2s[cl] - 2.0f * acc[mt][nt][j];
                float v1 = m2s[cl] - 2.0f * acc[mt][nt][2 + j];
                unsigned u0 = __float_as_uint(v0);
                u0 = (u0 & 0x80000000u) ? ~u0 : (u0 | 0x80000000u);
                unsigned u1 = __float_as_uint(v1);
                u1 = (u1 & 0x80000000u) ? ~u1 : (u1 | 0x80000000u);
                unsigned long long key0 = ((unsigned long long)u0 << 32) | (unsigned)(n0 + cl);
                unsigned long long key1 = ((unsigned long long)u1 << 32) | (unsigned)(n0 + cl);
                k0v = key0 < k0v ? key0 : k0v;
                k1v = key1 < k1v ? key1 : k1v;
            }
        }
        #pragma unroll
        for (int o = 1; o <= 2; o <<= 1) {
            unsigned long long t0 = __shfl_xor_sync(0xFFFFFFFFu, k0v, o);
            unsigned long long t1 = __shfl_xor_sync(0xFFFFFFFFu, k1v, o);
            k0v = t0 < k0v ? t0 : k0v;
            k1v = t1 < k1v ? t1 : k1v;
        }
        if (tig == 0) {
            atomicMin(&rowmin[rl], k0v);
            atomicMin(&rowmin[rl + 8], k1v);
        }
    }
    __syncthreads();
    if (tid < 128) atomicMin(&g_bmu[b0 + tid], rowmin[tid]);
}

// ---------------- K2: scatter ----------------
__global__ void k_scatter(const float* __restrict__ x) {
    int b = blockIdx.x;
    int p = (int)(g_bmu[b] & 0xFFFFFFFFull);
    if (threadIdx.x == 0) atomicAdd(&g_cnt[p], 1.0f);
    const float* xr = x + (size_t)b * DDIM;
    float* yr = g_Y + (size_t)p * DDIM;
    for (int d = threadIdx.x; d < DDIM; d += blockDim.x)
        atomicAdd(&yr[d], xr[d]);
}

// ---------------- K3: cs[n] separable + exact corner correction ----------------
__global__ __launch_bounds__(256) void k_colsum() {
    __shared__ float cnts[NODES];
    __shared__ float e[64];
    __shared__ float T2[64][65];
    int tid = threadIdx.x;
    int ni = blockIdx.x;
    float c2 = neg_inv_2r2();
    if (tid < 64) e[tid] = expf((float)(tid * tid) * c2);
    for (int i = tid; i < NODES; i += 256) cnts[i] = g_cnt[i];
    __syncthreads();
    for (int idx = tid; idx < 4096; idx += 256) {
        int pi = idx >> 6, nj = idx & 63;
        float s = 0.f;
        #pragma unroll 8
        for (int pj = 0; pj < 64; pj++) s += e[abs(pj - nj)] * cnts[pi * 64 + pj];
        T2[pi][nj] = s;
    }
    __syncthreads();
    int nj = tid >> 2, part = tid & 3;
    float s = 0.f;
    for (int pi = part; pi < GRIDW; pi += 4) {
        int di = pi - ni;
        float ei = e[abs(di)];
        s += ei * T2[pi][nj];
        int t = isqrt_le(D2_MAX - di * di);
        for (int pj = 0; pj <= nj - t - 1; pj++) s -= ei * e[nj - pj] * cnts[pi * 64 + pj];
        for (int pj = nj + t + 1; pj < GRIDW; pj++) s -= ei * e[pj - nj] * cnts[pi * 64 + pj];
    }
    s += __shfl_down_sync(0xFFFFFFFFu, s, 2);
    s += __shfl_down_sync(0xFFFFFFFFu, s, 1);
    if (part == 0) g_cs[ni * 64 + nj] = s;
}

// ---------------- K4a: conv over pj ----------------
__global__ __launch_bounds__(256) void k_convA() {
    __shared__ float Ys[64][128];
    __shared__ float e[64];
    int tid = threadIdx.x;
    int pi = blockIdx.y;
    int d0 = blockIdx.x * 128;
    float c2 = neg_inv_2r2();
    if (tid < 64) e[tid] = expf((float)(tid * tid) * c2);
    for (int i = tid; i < 2048; i += 256) {
        int row = i >> 5, c4 = (i & 31) * 4;
        *(float4*)&Ys[row][c4] = *(const float4*)(g_Y + ((size_t)pi * 64 + row) * DDIM + d0 + c4);
    }
    __syncthreads();
    int d4 = (tid & 31) * 4;
    int njb = tid >> 5;
    #pragma unroll
    for (int g = 0; g < 8; g++) {
        int nj = njb * 8 + g;
        float4 acc = make_float4(0.f, 0.f, 0.f, 0.f);
        #pragma unroll 8
        for (int pj = 0; pj < 64; pj++) {
            float w = e[abs(pj - nj)];
            float4 y = *(const float4*)&Ys[pj][d4];
            acc.x += w * y.x; acc.y += w * y.y; acc.z += w * y.z; acc.w += w * y.w;
        }
        *(float4*)(g_T + ((size_t)pi * 64 + nj) * DDIM + d0 + d4) = acc;
    }
}

// ---------------- K4b: conv over pi + fused update ----------------
__global__ __launch_bounds__(256) void k_convB(const float* __restrict__ mw,
                                               float* __restrict__ out) {
    __shared__ float Ts[64][128];
    __shared__ float e[64];
    __shared__ float css[64];
    int tid = threadIdx.x;
    int nj = blockIdx.y;
    int d0 = blockIdx.x * 128;
    float c2 = neg_inv_2r2();
    if (tid < 64) { e[tid] = expf((float)(tid * tid) * c2); css[tid] = g_cs[tid * 64 + nj]; }
    for (int i = tid; i < 2048; i += 256) {
        int row = i >> 5, c4 = (i & 31) * 4;
        *(float4*)&Ts[row][c4] = *(const float4*)(g_T + ((size_t)row * 64 + nj) * DDIM + d0 + c4);
    }
    __syncthreads();
    const float scale = 0.5f / 8192.0f;
    int d4 = (tid & 31) * 4;
    int nib = tid >> 5;
    #pragma unroll
    for (int g = 0; g < 8; g++) {
        int ni = nib * 8 + g;
        float4 acc = make_float4(0.f, 0.f, 0.f, 0.f);
        #pragma unroll 8
        for (int pi = 0; pi < 64; pi++) {
            float w = e[abs(pi - ni)];
            float4 t = *(const float4*)&Ts[pi][d4];
            acc.x += w * t.x; acc.y += w * t.y; acc.z += w * t.z; acc.w += w * t.w;
        }
        float cs = css[ni];
        size_t off = ((size_t)ni * 64 + nj) * DDIM + d0 + d4;
        float4 m = *(const float4*)(mw + off);
        float4 o;
        o.x = m.x + scale * (acc.x - cs * m.x);
        o.y = m.y + scale * (acc.y - cs * m.y);
        o.z = m.z + scale * (acc.z - cs * m.z);
        o.w = m.w + scale * (acc.w - cs * m.w);
        *(float4*)(out + off) = o;
    }
}

// ---------------- K4c: out-of-radius correction (corner nodes only) ----------------
__global__ __launch_bounds__(256) void k_corr(float* __restrict__ out) {
    int n = blockIdx.x;
    int ni = n >> 6, nj = n & 63;
    int u = max(ni, 63 - ni), v = max(nj, 63 - nj);
    if (u * u + v * v <= D2_MAX) return;
    __shared__ float e[64];
    int tid = threadIdx.x;
    float c2 = neg_inv_2r2();
    if (tid < 64) e[tid] = expf((float)(tid * tid) * c2);
    __syncthreads();
    int d4 = tid * 4;
    float4 acc = make_float4(0.f, 0.f, 0.f, 0.f);
    for (int pi = 0; pi < GRIDW; pi++) {
        int di = pi - ni;
        int t = isqrt_le(D2_MAX - di * di);
        float ei = e[abs(di)];
        for (int pj = 0; pj <= nj - t - 1; pj++) {
            float w = ei * e[nj - pj];
            float4 y = *(const float4*)(g_Y + ((size_t)pi * 64 + pj) * DDIM + d4);
            acc.x += w * y.x; acc.y += w * y.y; acc.z += w * y.z; acc.w += w * y.w;
        }
        for (int pj = nj + t + 1; pj < GRIDW; pj++) {
            float w = ei * e[pj - nj];
            float4 y = *(const float4*)(g_Y + ((size_t)pi * 64 + pj) * DDIM + d4);
            acc.x += w * y.x; acc.y += w * y.y; acc.z += w * y.z; acc.w += w * y.w;
        }
    }
    const float scale = 0.5f / 8192.0f;
    size_t off = (size_t)n * DDIM + d4;
    float4 o = *(float4*)(out + off);
    o.x -= scale * acc.x; o.y -= scale * acc.y; o.z -= scale * acc.z; o.w -= scale * acc.w;
    *(float4*)(out + off) = o;
}

// ---------------- launch ----------------
extern "C" void kernel_launch(void* const* d_in, const int* in_sizes, int n_in,
                              void* d_out, int out_size) {
    const float* x  = (const float*)d_in[0];
    const float* mw = (const float*)d_in[1];
    float* out = (float*)d_out;

    cudaFuncSetAttribute(k1_dist_argmin, cudaFuncAttributeMaxDynamicSharedMemorySize, K1_SMEM);

    k_init<<<NODES, 256>>>(mw);
    k_split<<<BSZ + NODES, 256>>>(x, mw);
    dim3 g1(NODES / 256, BSZ / 128);             // 16 x 64
    k1_dist_argmin<<<g1, 256, K1_SMEM>>>();
    k_scatter<<<BSZ, 256>>>(x);
    k_colsum<<<GRIDW, 256>>>();
    dim3 gc(DDIM / 128, GRIDW);
    k_convA<<<gc, 256>>>();
    k_convB<<<gc, 256>>>(mw, out);
    k_corr<<<NODES, 256>>>(out);
}

// round 7
// speedup vs baseline: 4.6609x; 1.5884x over previous
#include <cuda_runtime.h>
#include <cuda_fp16.h>
#include <cstdint>

#define BSZ   8192
#define DDIM  1024
#define NODES 4096
#define GRIDW 64
#define D2_MAX 4956          // integer d2 <= 4956 <=> sqrt(d2) <= radius (exact)
#define MARGIN 0.3f

// ---------------- scratch ----------------
__device__ unsigned long long g_bmu[BSZ];
__device__ float g_S[(size_t)BSZ * NODES];     // approx scores (128 MB)
__device__ float g_Y[NODES * DDIM];
__device__ float g_T[NODES * DDIM];
__device__ float g_cnt[NODES];
__device__ float g_m2[NODES];
__device__ float g_cs[NODES];
__device__ __half g_xh[BSZ * DDIM];
__device__ __half g_mh[NODES * DDIM];

__device__ __forceinline__ float neg_inv_2r2() {
    const float r = 70.4f + 1e-6f;
    return -1.0f / (2.0f * r * r);
}
static __device__ __forceinline__ uint32_t smem_u32(const void* p) {
    uint32_t a;
    asm("{ .reg .u64 t; cvta.to.shared.u64 t, %1; cvt.u32.u64 %0, t; }" : "=r"(a) : "l"(p));
    return a;
}
static __device__ __forceinline__ void mma_f16(float* c, const uint32_t* a, const uint32_t* b) {
    asm volatile(
        "mma.sync.aligned.m16n8k16.row.col.f32.f16.f16.f32 "
        "{%0,%1,%2,%3}, {%4,%5,%6,%7}, {%8,%9}, {%0,%1,%2,%3};"
        : "+f"(c[0]), "+f"(c[1]), "+f"(c[2]), "+f"(c[3])
        : "r"(a[0]), "r"(a[1]), "r"(a[2]), "r"(a[3]), "r"(b[0]), "r"(b[1]));
}
static __device__ __forceinline__ void ldsm_x4(uint32_t* r, uint32_t addr) {
    asm volatile("ldmatrix.sync.aligned.m8n8.x4.shared.b16 {%0,%1,%2,%3}, [%4];"
                 : "=r"(r[0]), "=r"(r[1]), "=r"(r[2]), "=r"(r[3]) : "r"(addr));
}
static __device__ __forceinline__ void cp16(uint32_t dst, const void* src) {
    asm volatile("cp.async.cg.shared.global [%0], [%1], 16;" :: "r"(dst), "l"(src));
}
#define CP_COMMIT() asm volatile("cp.async.commit_group;" ::: "memory")
#define CP_WAIT1()  asm volatile("cp.async.wait_group 1;" ::: "memory")

static __device__ __forceinline__ int isqrt_le(int rem) {
    int t = (int)sqrtf((float)rem);
    while (t * t > rem) --t;
    while ((t + 1) * (t + 1) <= rem) ++t;
    return t;
}
static __device__ __forceinline__ unsigned ofloat(float v) {
    unsigned u = __float_as_uint(v);
    return (u & 0x80000000u) ? ~u : (u | 0x80000000u);
}

// ---------------- K0: init (zero Y/cnt, compute m2) ----------------
__global__ void k_init(const float* __restrict__ mw) {
    int tid = threadIdx.x, bid = blockIdx.x;
    int gidx = bid * 256 + tid;
    ((float4*)g_Y)[gidx] = make_float4(0.f, 0.f, 0.f, 0.f);
    if (gidx < NODES) g_cnt[gidx] = 0.f;

    float4 v = ((const float4*)(mw + (size_t)bid * DDIM))[tid];
    float s = v.x * v.x + v.y * v.y + v.z * v.z + v.w * v.w;
    #pragma unroll
    for (int o = 16; o; o >>= 1) s += __shfl_down_sync(0xFFFFFFFFu, s, o);
    __shared__ float ws[8];
    if ((tid & 31) == 0) ws[tid >> 5] = s;
    __syncthreads();
    if (tid == 0) {
        float t = 0.f;
        #pragma unroll
        for (int i = 0; i < 8; i++) t += ws[i];
        g_m2[bid] = t;
    }
}

// ---------------- K0b: fp32 -> fp16 (hi only) ----------------
__global__ void k_split(const float* __restrict__ x, const float* __restrict__ mw) {
    int r = blockIdx.x, tid = threadIdx.x;
    const float* src;
    __half* dh;
    if (r < BSZ) { src = x + (size_t)r * DDIM; dh = g_xh + (size_t)r * DDIM; }
    else { int m = r - BSZ; src = mw + (size_t)m * DDIM; dh = g_mh + (size_t)m * DDIM; }
    float4 v = ((const float4*)src)[tid];
    ((__half2*)dh)[tid * 2]     = __halves2half2(__float2half_rn(v.x), __float2half_rn(v.y));
    ((__half2*)dh)[tid * 2 + 1] = __halves2half2(__float2half_rn(v.z), __float2half_rn(v.w));
}

// ---------------- K1a: single fp16 MMA pass, write approx scores ----------------
// CTA tile 128m x 256n, warp tile 64x64, 3-stage cp.async pipeline, pitch 40 halves.
#define K1_PITCH 40
#define K1_STAGE 15360          // halves: Ah 128*40 + Bh 256*40
#define K1_HALVES (3 * K1_STAGE)
#define K1_SMEM (K1_HALVES * 2 + 1024)
__global__ void __launch_bounds__(256, 1) k1a_score() {
    extern __shared__ __half sh[];
    float* m2s = (float*)(sh + K1_HALVES);
    uint32_t sbase = smem_u32(sh);

    int tid = threadIdx.x;
    int lane = tid & 31, wid = tid >> 5;
    int warpM = wid & 1, warpN = wid >> 1;
    int gid = lane >> 2, tig = lane & 3;
    int lrow = lane & 15, lsel = (lane >> 4) * 8;
    int n0 = blockIdx.x * 256, b0 = blockIdx.y * 128;

    m2s[tid] = g_m2[n0 + tid];

    float acc[4][8][4];
    #pragma unroll
    for (int a = 0; a < 4; a++)
        #pragma unroll
        for (int b = 0; b < 8; b++)
            #pragma unroll
            for (int c = 0; c < 4; c++) acc[a][b][c] = 0.f;

    auto load_tile = [&](int i) {
        int s = i % 3;
        int k0 = i * 32;
        uint32_t stage = sbase + 2u * (uint32_t)(s * K1_STAGE);
        #pragma unroll
        for (int u = 0; u < 2; u++) {            // A: 512 chunks
            int ch = tid + u * 256;
            int row = ch >> 2, kc = (ch & 3) * 8;
            cp16(stage + 2u * (uint32_t)(row * K1_PITCH + kc),
                 g_xh + (size_t)(b0 + row) * DDIM + k0 + kc);
        }
        #pragma unroll
        for (int u = 0; u < 4; u++) {            // B: 1024 chunks
            int ch = tid + u * 256;
            int row = ch >> 2, kc = (ch & 3) * 8;
            cp16(stage + 2u * (uint32_t)(5120 + row * K1_PITCH + kc),
                 g_mh + (size_t)(n0 + row) * DDIM + k0 + kc);
        }
    };

    load_tile(0); CP_COMMIT();
    load_tile(1); CP_COMMIT();

    for (int i = 0; i < 32; i++) {
        CP_WAIT1();
        __syncthreads();
        if (i + 2 < 32) load_tile(i + 2);
        CP_COMMIT();

        uint32_t stage = sbase + 2u * (uint32_t)((i % 3) * K1_STAGE);
        #pragma unroll
        for (int ks = 0; ks < 2; ks++) {
            int kb = ks * 16;
            uint32_t ah[4][4];
            #pragma unroll
            for (int mt = 0; mt < 4; mt++)
                ldsm_x4(ah[mt], stage + 2u * (uint32_t)((warpM * 64 + mt * 16 + lrow) * K1_PITCH + kb + lsel));
            uint32_t bh[8][2];
            #pragma unroll
            for (int pr = 0; pr < 4; pr++) {
                uint32_t t[4];
                ldsm_x4(t, stage + 2u * (uint32_t)(5120 + (warpN * 64 + pr * 16 + lrow) * K1_PITCH + kb + lsel));
                bh[pr * 2][0] = t[0]; bh[pr * 2 + 1][0] = t[1];
                bh[pr * 2][1] = t[2]; bh[pr * 2 + 1][1] = t[3];
            }
            #pragma unroll
            for (int mt = 0; mt < 4; mt++)
                #pragma unroll
                for (int nt = 0; nt < 8; nt++)
                    mma_f16(acc[mt][nt], ah[mt], bh[nt]);
        }
    }

    // write scores
    #pragma unroll
    for (int mt = 0; mt < 4; mt++) {
        int r0 = b0 + warpM * 64 + mt * 16 + gid;
        #pragma unroll
        for (int nt = 0; nt < 8; nt++) {
            int cl = warpN * 64 + nt * 8 + tig * 2;
            float2 s0, s1;
            s0.x = m2s[cl]     - 2.0f * acc[mt][nt][0];
            s0.y = m2s[cl + 1] - 2.0f * acc[mt][nt][1];
            s1.x = m2s[cl]     - 2.0f * acc[mt][nt][2];
            s1.y = m2s[cl + 1] - 2.0f * acc[mt][nt][3];
            *(float2*)(g_S + (size_t)r0 * NODES + n0 + cl) = s0;
            *(float2*)(g_S + (size_t)(r0 + 8) * NODES + n0 + cl) = s1;
        }
    }
}

// ---------------- K1b: per-row scan + exact fp32 refinement ----------------
__global__ void __launch_bounds__(256) k1b_refine(const float* __restrict__ x,
                                                  const float* __restrict__ mw) {
    __shared__ float xs[DDIM];
    __shared__ unsigned wmin[8];
    __shared__ float red[8];
    __shared__ int cand[128];
    __shared__ int ncand;
    __shared__ float bestval;
    __shared__ unsigned long long bkey;

    int b = blockIdx.x, tid = threadIdx.x;
    int lane = tid & 31, wid = tid >> 5;
    const float* Srow = g_S + (size_t)b * NODES;

    if (tid == 0) { ncand = 0; bkey = 0xFFFFFFFFFFFFFFFFull; }

    // 1) approx min (value only)
    float vmin = 3.4e38f;
    float sv[16];
    #pragma unroll
    for (int q = 0; q < 16; q++) {
        sv[q] = Srow[tid + q * 256];
        vmin = fminf(vmin, sv[q]);
    }
    unsigned key = ofloat(vmin);
    #pragma unroll
    for (int o = 16; o; o >>= 1) {
        unsigned t = __shfl_down_sync(0xFFFFFFFFu, key, o);
        key = t < key ? t : key;
    }
    if (lane == 0) wmin[wid] = key;
    // 3) load x row (overlap with reduce)
    #pragma unroll
    for (int q = 0; q < 4; q++) xs[tid + q * 256] = x[(size_t)b * DDIM + tid + q * 256];
    __syncthreads();
    if (tid == 0) {
        unsigned m = wmin[0];
        #pragma unroll
        for (int i = 1; i < 8; i++) m = wmin[i] < m ? wmin[i] : m;
        unsigned u = (m & 0x80000000u) ? (m & 0x7FFFFFFFu) : ~m;
        bestval = __uint_as_float(u);
    }
    __syncthreads();

    // 2) candidates within margin
    float th = bestval + MARGIN;
    #pragma unroll
    for (int q = 0; q < 16; q++) {
        if (sv[q] <= th) {
            int pos = atomicAdd(&ncand, 1);
            if (pos < 128) cand[pos] = tid + q * 256;
        }
    }
    __syncthreads();

    // 4) exact fp32 refine
    int nc = min(ncand, 128);
    for (int c = 0; c < nc; c++) {
        int n = cand[c];
        const float* mr = mw + (size_t)n * DDIM;
        float p = 0.f;
        #pragma unroll
        for (int q = 0; q < 4; q++) p += xs[tid + q * 256] * mr[tid + q * 256];
        #pragma unroll
        for (int o = 16; o; o >>= 1) p += __shfl_down_sync(0xFFFFFFFFu, p, o);
        if (lane == 0) red[wid] = p;
        __syncthreads();
        if (tid == 0) {
            float dot = 0.f;
            #pragma unroll
            for (int i = 0; i < 8; i++) dot += red[i];
            float sc = g_m2[n] - 2.0f * dot;
            unsigned long long k = ((unsigned long long)ofloat(sc) << 32) | (unsigned)n;
            if (k < bkey) bkey = k;
        }
        __syncthreads();
    }
    if (tid == 0) g_bmu[b] = bkey;
}

// ---------------- K2: scatter ----------------
__global__ void k_scatter(const float* __restrict__ x) {
    int b = blockIdx.x;
    int p = (int)(g_bmu[b] & 0xFFFFFFFFull);
    if (threadIdx.x == 0) atomicAdd(&g_cnt[p], 1.0f);
    const float* xr = x + (size_t)b * DDIM;
    float* yr = g_Y + (size_t)p * DDIM;
    for (int d = threadIdx.x; d < DDIM; d += blockDim.x)
        atomicAdd(&yr[d], xr[d]);
}

// ---------------- K3: cs[n] separable + exact corner correction ----------------
__global__ __launch_bounds__(256) void k_colsum() {
    __shared__ float cnts[NODES];
    __shared__ float e[64];
    __shared__ float T2[64][65];
    int tid = threadIdx.x;
    int ni = blockIdx.x;
    float c2 = neg_inv_2r2();
    if (tid < 64) e[tid] = expf((float)(tid * tid) * c2);
    for (int i = tid; i < NODES; i += 256) cnts[i] = g_cnt[i];
    __syncthreads();
    for (int idx = tid; idx < 4096; idx += 256) {
        int pi = idx >> 6, nj = idx & 63;
        float s = 0.f;
        #pragma unroll 8
        for (int pj = 0; pj < 64; pj++) s += e[abs(pj - nj)] * cnts[pi * 64 + pj];
        T2[pi][nj] = s;
    }
    __syncthreads();
    int nj = tid >> 2, part = tid & 3;
    float s = 0.f;
    for (int pi = part; pi < GRIDW; pi += 4) {
        int di = pi - ni;
        float ei = e[abs(di)];
        s += ei * T2[pi][nj];
        int t = isqrt_le(D2_MAX - di * di);
        for (int pj = 0; pj <= nj - t - 1; pj++) s -= ei * e[nj - pj] * cnts[pi * 64 + pj];
        for (int pj = nj + t + 1; pj < GRIDW; pj++) s -= ei * e[pj - nj] * cnts[pi * 64 + pj];
    }
    s += __shfl_down_sync(0xFFFFFFFFu, s, 2);
    s += __shfl_down_sync(0xFFFFFFFFu, s, 1);
    if (part == 0) g_cs[ni * 64 + nj] = s;
}

// ---------------- K4a: conv over pj ----------------
__global__ __launch_bounds__(256) void k_convA() {
    __shared__ float Ys[64][128];
    __shared__ float e[64];
    int tid = threadIdx.x;
    int pi = blockIdx.y;
    int d0 = blockIdx.x * 128;
    float c2 = neg_inv_2r2();
    if (tid < 64) e[tid] = expf((float)(tid * tid) * c2);
    for (int i = tid; i < 2048; i += 256) {
        int row = i >> 5, c4 = (i & 31) * 4;
        *(float4*)&Ys[row][c4] = *(const float4*)(g_Y + ((size_t)pi * 64 + row) * DDIM + d0 + c4);
    }
    __syncthreads();
    int d4 = (tid & 31) * 4;
    int njb = tid >> 5;
    #pragma unroll
    for (int g = 0; g < 8; g++) {
        int nj = njb * 8 + g;
        float4 acc = make_float4(0.f, 0.f, 0.f, 0.f);
        #pragma unroll 8
        for (int pj = 0; pj < 64; pj++) {
            float w = e[abs(pj - nj)];
            float4 y = *(const float4*)&Ys[pj][d4];
            acc.x += w * y.x; acc.y += w * y.y; acc.z += w * y.z; acc.w += w * y.w;
        }
        *(float4*)(g_T + ((size_t)pi * 64 + nj) * DDIM + d0 + d4) = acc;
    }
}

// ---------------- K4b: conv over pi + fused update ----------------
__global__ __launch_bounds__(256) void k_convB(const float* __restrict__ mw,
                                               float* __restrict__ out) {
    __shared__ float Ts[64][128];
    __shared__ float e[64];
    __shared__ float css[64];
    int tid = threadIdx.x;
    int nj = blockIdx.y;
    int d0 = blockIdx.x * 128;
    float c2 = neg_inv_2r2();
    if (tid < 64) { e[tid] = expf((float)(tid * tid) * c2); css[tid] = g_cs[tid * 64 + nj]; }
    for (int i = tid; i < 2048; i += 256) {
        int row = i >> 5, c4 = (i & 31) * 4;
        *(float4*)&Ts[row][c4] = *(const float4*)(g_T + ((size_t)row * 64 + nj) * DDIM + d0 + c4);
    }
    __syncthreads();
    const float scale = 0.5f / 8192.0f;
    int d4 = (tid & 31) * 4;
    int nib = tid >> 5;
    #pragma unroll
    for (int g = 0; g < 8; g++) {
        int ni = nib * 8 + g;
        float4 acc = make_float4(0.f, 0.f, 0.f, 0.f);
        #pragma unroll 8
        for (int pi = 0; pi < 64; pi++) {
            float w = e[abs(pi - ni)];
            float4 t = *(const float4*)&Ts[pi][d4];
            acc.x += w * t.x; acc.y += w * t.y; acc.z += w * t.z; acc.w += w * t.w;
        }
        float cs = css[ni];
        size_t off = ((size_t)ni * 64 + nj) * DDIM + d0 + d4;
        float4 m = *(const float4*)(mw + off);
        float4 o;
        o.x = m.x + scale * (acc.x - cs * m.x);
        o.y = m.y + scale * (acc.y - cs * m.y);
        o.z = m.z + scale * (acc.z - cs * m.z);
        o.w = m.w + scale * (acc.w - cs * m.w);
        *(float4*)(out + off) = o;
    }
}

// ---------------- K4c: out-of-radius correction (corner nodes only) ----------------
__global__ __launch_bounds__(256) void k_corr(float* __restrict__ out) {
    int n = blockIdx.x;
    int ni = n >> 6, nj = n & 63;
    int u = max(ni, 63 - ni), v = max(nj, 63 - nj);
    if (u * u + v * v <= D2_MAX) return;
    __shared__ float e[64];
    int tid = threadIdx.x;
    float c2 = neg_inv_2r2();
    if (tid < 64) e[tid] = expf((float)(tid * tid) * c2);
    __syncthreads();
    int d4 = tid * 4;
    float4 acc = make_float4(0.f, 0.f, 0.f, 0.f);
    for (int pi = 0; pi < GRIDW; pi++) {
        int di = pi - ni;
        int t = isqrt_le(D2_MAX - di * di);
        float ei = e[abs(di)];
        for (int pj = 0; pj <= nj - t - 1; pj++) {
            float w = ei * e[nj - pj];
            float4 y = *(const float4*)(g_Y + ((size_t)pi * 64 + pj) * DDIM + d4);
            acc.x += w * y.x; acc.y += w * y.y; acc.z += w * y.z; acc.w += w * y.w;
        }
        for (int pj = nj + t + 1; pj < GRIDW; pj++) {
            float w = ei * e[pj - nj];
            float4 y = *(const float4*)(g_Y + ((size_t)pi * 64 + pj) * DDIM + d4);
            acc.x += w * y.x; acc.y += w * y.y; acc.z += w * y.z; acc.w += w * y.w;
        }
    }
    const float scale = 0.5f / 8192.0f;
    size_t off = (size_t)n * DDIM + d4;
    float4 o = *(float4*)(out + off);
    o.x -= scale * acc.x; o.y -= scale * acc.y; o.z -= scale * acc.z; o.w -= scale * acc.w;
    *(float4*)(out + off) = o;
}

// ---------------- launch ----------------
extern "C" void kernel_launch(void* const* d_in, const int* in_sizes, int n_in,
                              void* d_out, int out_size) {
    const float* x  = (const float*)d_in[0];
    const float* mw = (const float*)d_in[1];
    float* out = (float*)d_out;

    cudaFuncSetAttribute(k1a_score, cudaFuncAttributeMaxDynamicSharedMemorySize, K1_SMEM);

    k_init<<<NODES, 256>>>(mw);
    k_split<<<BSZ + NODES, 256>>>(x, mw);
    dim3 g1(NODES / 256, BSZ / 128);             // 16 x 64
    k1a_score<<<g1, 256, K1_SMEM>>>();
    k1b_refine<<<BSZ, 256>>>(x, mw);
    k_scatter<<<BSZ, 256>>>(x);
    k_colsum<<<GRIDW, 256>>>();
    dim3 gc(DDIM / 128, GRIDW);
    k_convA<<<gc, 256>>>();
    k_convB<<<gc, 256>>>(mw, out);
    k_corr<<<NODES, 256>>>(out);
}

// round 8
// speedup vs baseline: 5.0227x; 1.0776x over previous
#include <cuda_runtime.h>
#include <cuda_fp16.h>
#include <cstdint>

#define BSZ   8192
#define DDIM  1024
#define NODES 4096
#define GRIDW 64
#define D2_MAX 4956          // integer d2 <= 4956 <=> sqrt(d2) <= radius (exact)
#define MARGIN 0.6f

// ---------------- scratch ----------------
__device__ unsigned long long g_bmu[BSZ];
__device__ __half g_Sh[(size_t)BSZ * NODES];   // approx scores fp16 (64 MB)
__device__ unsigned g_tmin[BSZ * 16];          // per-row per-tile min (ordered u32)
__device__ float g_Y[NODES * DDIM];
__device__ float g_T[NODES * DDIM];
__device__ float g_cnt[NODES];
__device__ float g_m2[NODES];
__device__ float g_cs[NODES];
__device__ __half g_xh[BSZ * DDIM];
__device__ __half g_mh[NODES * DDIM];

__device__ __forceinline__ float neg_inv_2r2() {
    const float r = 70.4f + 1e-6f;
    return -1.0f / (2.0f * r * r);
}
static __device__ __forceinline__ uint32_t smem_u32(const void* p) {
    uint32_t a;
    asm("{ .reg .u64 t; cvta.to.shared.u64 t, %1; cvt.u32.u64 %0, t; }" : "=r"(a) : "l"(p));
    return a;
}
static __device__ __forceinline__ void mma_f16(float* c, const uint32_t* a, const uint32_t* b) {
    asm volatile(
        "mma.sync.aligned.m16n8k16.row.col.f32.f16.f16.f32 "
        "{%0,%1,%2,%3}, {%4,%5,%6,%7}, {%8,%9}, {%0,%1,%2,%3};"
        : "+f"(c[0]), "+f"(c[1]), "+f"(c[2]), "+f"(c[3])
        : "r"(a[0]), "r"(a[1]), "r"(a[2]), "r"(a[3]), "r"(b[0]), "r"(b[1]));
}
static __device__ __forceinline__ void ldsm_x4(uint32_t* r, uint32_t addr) {
    asm volatile("ldmatrix.sync.aligned.m8n8.x4.shared.b16 {%0,%1,%2,%3}, [%4];"
                 : "=r"(r[0]), "=r"(r[1]), "=r"(r[2]), "=r"(r[3]) : "r"(addr));
}
static __device__ __forceinline__ void cp16(uint32_t dst, const void* src) {
    asm volatile("cp.async.cg.shared.global [%0], [%1], 16;" :: "r"(dst), "l"(src));
}
#define CP_COMMIT() asm volatile("cp.async.commit_group;" ::: "memory")
#define CP_WAIT1()  asm volatile("cp.async.wait_group 1;" ::: "memory")

static __device__ __forceinline__ int isqrt_le(int rem) {
    int t = (int)sqrtf((float)rem);
    while (t * t > rem) --t;
    while ((t + 1) * (t + 1) <= rem) ++t;
    return t;
}
static __device__ __forceinline__ unsigned ofloat(float v) {
    unsigned u = __float_as_uint(v);
    return (u & 0x80000000u) ? ~u : (u | 0x80000000u);
}
static __device__ __forceinline__ float defloat(unsigned m) {
    unsigned u = (m & 0x80000000u) ? (m & 0x7FFFFFFFu) : ~m;
    return __uint_as_float(u);
}

// ---------------- K0: init (zero Y/cnt, compute m2) ----------------
__global__ void k_init(const float* __restrict__ mw) {
    int tid = threadIdx.x, bid = blockIdx.x;
    int gidx = bid * 256 + tid;
    ((float4*)g_Y)[gidx] = make_float4(0.f, 0.f, 0.f, 0.f);
    if (gidx < NODES) g_cnt[gidx] = 0.f;

    float4 v = ((const float4*)(mw + (size_t)bid * DDIM))[tid];
    float s = v.x * v.x + v.y * v.y + v.z * v.z + v.w * v.w;
    #pragma unroll
    for (int o = 16; o; o >>= 1) s += __shfl_down_sync(0xFFFFFFFFu, s, o);
    __shared__ float ws[8];
    if ((tid & 31) == 0) ws[tid >> 5] = s;
    __syncthreads();
    if (tid == 0) {
        float t = 0.f;
        #pragma unroll
        for (int i = 0; i < 8; i++) t += ws[i];
        g_m2[bid] = t;
    }
}

// ---------------- K0b: fp32 -> fp16 ----------------
__global__ void k_split(const float* __restrict__ x, const float* __restrict__ mw) {
    int r = blockIdx.x, tid = threadIdx.x;
    const float* src;
    __half* dh;
    if (r < BSZ) { src = x + (size_t)r * DDIM; dh = g_xh + (size_t)r * DDIM; }
    else { int m = r - BSZ; src = mw + (size_t)m * DDIM; dh = g_mh + (size_t)m * DDIM; }
    float4 v = ((const float4*)src)[tid];
    ((__half2*)dh)[tid * 2]     = __halves2half2(__float2half_rn(v.x), __float2half_rn(v.y));
    ((__half2*)dh)[tid * 2 + 1] = __halves2half2(__float2half_rn(v.z), __float2half_rn(v.w));
}

// ---------------- K1a: fp16 MMA pass -> fp16 scores + per-tile row mins ----------------
#define K1_PITCH 40
#define K1_STAGE 15360
#define K1_HALVES (3 * K1_STAGE)
#define K1_SMEM (K1_HALVES * 2 + 1024)
__global__ void __launch_bounds__(256, 1) k1a_score() {
    extern __shared__ __half sh[];
    float* m2s = (float*)(sh + K1_HALVES);
    __shared__ unsigned rowmin[128];
    uint32_t sbase = smem_u32(sh);

    int tid = threadIdx.x;
    int lane = tid & 31, wid = tid >> 5;
    int warpM = wid & 1, warpN = wid >> 1;
    int gid = lane >> 2, tig = lane & 3;
    int lrow = lane & 15, lsel = (lane >> 4) * 8;
    int n0 = blockIdx.x * 256, b0 = blockIdx.y * 128;

    m2s[tid] = g_m2[n0 + tid];
    if (tid < 128) rowmin[tid] = 0xFFFFFFFFu;

    float acc[4][8][4];
    #pragma unroll
    for (int a = 0; a < 4; a++)
        #pragma unroll
        for (int b = 0; b < 8; b++)
            #pragma unroll
            for (int c = 0; c < 4; c++) acc[a][b][c] = 0.f;

    auto load_tile = [&](int i) {
        int s = i % 3;
        int k0 = i * 32;
        uint32_t stage = sbase + 2u * (uint32_t)(s * K1_STAGE);
        #pragma unroll
        for (int u = 0; u < 2; u++) {
            int ch = tid + u * 256;
            int row = ch >> 2, kc = (ch & 3) * 8;
            cp16(stage + 2u * (uint32_t)(row * K1_PITCH + kc),
                 g_xh + (size_t)(b0 + row) * DDIM + k0 + kc);
        }
        #pragma unroll
        for (int u = 0; u < 4; u++) {
            int ch = tid + u * 256;
            int row = ch >> 2, kc = (ch & 3) * 8;
            cp16(stage + 2u * (uint32_t)(5120 + row * K1_PITCH + kc),
                 g_mh + (size_t)(n0 + row) * DDIM + k0 + kc);
        }
    };

    load_tile(0); CP_COMMIT();
    load_tile(1); CP_COMMIT();

    for (int i = 0; i < 32; i++) {
        CP_WAIT1();
        __syncthreads();
        if (i + 2 < 32) load_tile(i + 2);
        CP_COMMIT();

        uint32_t stage = sbase + 2u * (uint32_t)((i % 3) * K1_STAGE);
        #pragma unroll
        for (int ks = 0; ks < 2; ks++) {
            int kb = ks * 16;
            uint32_t ah[4][4];
            #pragma unroll
            for (int mt = 0; mt < 4; mt++)
                ldsm_x4(ah[mt], stage + 2u * (uint32_t)((warpM * 64 + mt * 16 + lrow) * K1_PITCH + kb + lsel));
            uint32_t bh[8][2];
            #pragma unroll
            for (int pr = 0; pr < 4; pr++) {
                uint32_t t[4];
                ldsm_x4(t, stage + 2u * (uint32_t)(5120 + (warpN * 64 + pr * 16 + lrow) * K1_PITCH + kb + lsel));
                bh[pr * 2][0] = t[0]; bh[pr * 2 + 1][0] = t[1];
                bh[pr * 2][1] = t[2]; bh[pr * 2 + 1][1] = t[3];
            }
            #pragma unroll
            for (int mt = 0; mt < 4; mt++)
                #pragma unroll
                for (int nt = 0; nt < 8; nt++)
                    mma_f16(acc[mt][nt], ah[mt], bh[nt]);
        }
    }

    // epilogue: fp16 scores + per-row min (over this 256-col tile)
    #pragma unroll
    for (int mt = 0; mt < 4; mt++) {
        int rl = warpM * 64 + mt * 16 + gid;
        int r0 = b0 + rl;
        unsigned umin0 = 0xFFFFFFFFu, umin1 = 0xFFFFFFFFu;
        #pragma unroll
        for (int nt = 0; nt < 8; nt++) {
            int cl = warpN * 64 + nt * 8 + tig * 2;
            float a0 = m2s[cl]     - 2.0f * acc[mt][nt][0];
            float a1 = m2s[cl + 1] - 2.0f * acc[mt][nt][1];
            float a2 = m2s[cl]     - 2.0f * acc[mt][nt][2];
            float a3 = m2s[cl + 1] - 2.0f * acc[mt][nt][3];
            __half2 h0 = __floats2half2_rn(a0, a1);
            __half2 h1 = __floats2half2_rn(a2, a3);
            *(__half2*)(g_Sh + (size_t)r0 * NODES + n0 + cl) = h0;
            *(__half2*)(g_Sh + (size_t)(r0 + 8) * NODES + n0 + cl) = h1;
            unsigned u;
            u = ofloat(__low2float(h0));  umin0 = u < umin0 ? u : umin0;
            u = ofloat(__high2float(h0)); umin0 = u < umin0 ? u : umin0;
            u = ofloat(__low2float(h1));  umin1 = u < umin1 ? u : umin1;
            u = ofloat(__high2float(h1)); umin1 = u < umin1 ? u : umin1;
        }
        atomicMin(&rowmin[rl], umin0);
        atomicMin(&rowmin[rl + 8], umin1);
    }
    __syncthreads();
    if (tid < 128) g_tmin[(size_t)(b0 + tid) * 16 + blockIdx.x] = rowmin[tid];
}

// ---------------- K1b: tile-min screen + exact fp32 refinement ----------------
__global__ void __launch_bounds__(256) k1b_refine(const float* __restrict__ x,
                                                  const float* __restrict__ mw) {
    __shared__ float xs[DDIM];
    __shared__ unsigned tm[16];
    __shared__ float red[8];
    __shared__ int cand[64];
    __shared__ int ncand;
    __shared__ float thr;
    __shared__ unsigned long long bkey;

    int b = blockIdx.x, tid = threadIdx.x;
    int lane = tid & 31, wid = tid >> 5;

    if (tid < 16) tm[tid] = g_tmin[(size_t)b * 16 + tid];
    if (tid == 0) { ncand = 0; bkey = 0xFFFFFFFFFFFFFFFFull; }
    #pragma unroll
    for (int q = 0; q < 4; q++) xs[tid + q * 256] = x[(size_t)b * DDIM + tid + q * 256];
    __syncthreads();
    if (tid == 0) {
        unsigned m = tm[0];
        #pragma unroll
        for (int i = 1; i < 16; i++) m = tm[i] < m ? tm[i] : m;
        thr = defloat(m) + MARGIN;
    }
    __syncthreads();

    float th = thr;
    const __half* Srow = g_Sh + (size_t)b * NODES;
    for (int t = 0; t < 16; t++) {
        if (defloat(tm[t]) > th) continue;
        float v = __half2float(Srow[t * 256 + tid]);
        if (v <= th) {
            int pos = atomicAdd(&ncand, 1);
            if (pos < 64) cand[pos] = t * 256 + tid;
        }
    }
    __syncthreads();

    int nc = min(ncand, 64);
    for (int c = 0; c < nc; c++) {
        int n = cand[c];
        const float* mr = mw + (size_t)n * DDIM;
        float p = 0.f;
        #pragma unroll
        for (int q = 0; q < 4; q++) p += xs[tid + q * 256] * mr[tid + q * 256];
        #pragma unroll
        for (int o = 16; o; o >>= 1) p += __shfl_down_sync(0xFFFFFFFFu, p, o);
        if (lane == 0) red[wid] = p;
        __syncthreads();
        if (tid == 0) {
            float dot = 0.f;
            #pragma unroll
            for (int i = 0; i < 8; i++) dot += red[i];
            float sc = g_m2[n] - 2.0f * dot;
            unsigned long long k = ((unsigned long long)ofloat(sc) << 32) | (unsigned)n;
            if (k < bkey) bkey = k;
        }
        __syncthreads();
    }
    if (tid == 0) g_bmu[b] = bkey;
}

// ---------------- K2: scatter ----------------
__global__ void k_scatter(const float* __restrict__ x) {
    int b = blockIdx.x;
    int p = (int)(g_bmu[b] & 0xFFFFFFFFull);
    if (threadIdx.x == 0) atomicAdd(&g_cnt[p], 1.0f);
    const float* xr = x + (size_t)b * DDIM;
    float* yr = g_Y + (size_t)p * DDIM;
    for (int d = threadIdx.x; d < DDIM; d += blockDim.x)
        atomicAdd(&yr[d], xr[d]);
}

// ---------------- K3: cs[n] separable + exact corner correction ----------------
__global__ __launch_bounds__(256) void k_colsum() {
    __shared__ float cnts[NODES];
    __shared__ float e[64];
    __shared__ float T2[64][65];
    int tid = threadIdx.x;
    int ni = blockIdx.x;
    float c2 = neg_inv_2r2();
    if (tid < 64) e[tid] = expf((float)(tid * tid) * c2);
    for (int i = tid; i < NODES; i += 256) cnts[i] = g_cnt[i];
    __syncthreads();
    for (int idx = tid; idx < 4096; idx += 256) {
        int pi = idx >> 6, nj = idx & 63;
        float s = 0.f;
        #pragma unroll 8
        for (int pj = 0; pj < 64; pj++) s += e[abs(pj - nj)] * cnts[pi * 64 + pj];
        T2[pi][nj] = s;
    }
    __syncthreads();
    int nj = tid >> 2, part = tid & 3;
    float s = 0.f;
    for (int pi = part; pi < GRIDW; pi += 4) {
        int di = pi - ni;
        float ei = e[abs(di)];
        s += ei * T2[pi][nj];
        int t = isqrt_le(D2_MAX - di * di);
        for (int pj = 0; pj <= nj - t - 1; pj++) s -= ei * e[nj - pj] * cnts[pi * 64 + pj];
        for (int pj = nj + t + 1; pj < GRIDW; pj++) s -= ei * e[pj - nj] * cnts[pi * 64 + pj];
    }
    s += __shfl_down_sync(0xFFFFFFFFu, s, 2);
    s += __shfl_down_sync(0xFFFFFFFFu, s, 1);
    if (part == 0) g_cs[ni * 64 + nj] = s;
}

// ---------------- K4a: conv over pj (pj-outer, 8 accumulators) ----------------
__global__ __launch_bounds__(256) void k_convA() {
    __shared__ float Ys[64][128];
    __shared__ float e[64];
    int tid = threadIdx.x;
    int pi = blockIdx.y;
    int d0 = blockIdx.x * 128;
    float c2 = neg_inv_2r2();
    if (tid < 64) e[tid] = expf((float)(tid * tid) * c2);
    for (int i = tid; i < 2048; i += 256) {
        int row = i >> 5, c4 = (i & 31) * 4;
        *(float4*)&Ys[row][c4] = *(const float4*)(g_Y + ((size_t)pi * 64 + row) * DDIM + d0 + c4);
    }
    __syncthreads();
    int d4 = (tid & 31) * 4;
    int njb = tid >> 5;
    float4 a8[8];
    #pragma unroll
    for (int g = 0; g < 8; g++) a8[g] = make_float4(0.f, 0.f, 0.f, 0.f);
    for (int pj = 0; pj < 64; pj++) {
        float4 y = *(const float4*)&Ys[pj][d4];
        #pragma unroll
        for (int g = 0; g < 8; g++) {
            float w = e[abs(pj - (njb * 8 + g))];
            a8[g].x += w * y.x; a8[g].y += w * y.y; a8[g].z += w * y.z; a8[g].w += w * y.w;
        }
    }
    #pragma unroll
    for (int g = 0; g < 8; g++)
        *(float4*)(g_T + ((size_t)pi * 64 + njb * 8 + g) * DDIM + d0 + d4) = a8[g];
}

// ---------------- K4b: conv over pi + fused update (pi-outer) ----------------
__global__ __launch_bounds__(256) void k_convB(const float* __restrict__ mw,
                                               float* __restrict__ out) {
    __shared__ float Ts[64][128];
    __shared__ float e[64];
    __shared__ float css[64];
    int tid = threadIdx.x;
    int nj = blockIdx.y;
    int d0 = blockIdx.x * 128;
    float c2 = neg_inv_2r2();
    if (tid < 64) { e[tid] = expf((float)(tid * tid) * c2); css[tid] = g_cs[tid * 64 + nj]; }
    for (int i = tid; i < 2048; i += 256) {
        int row = i >> 5, c4 = (i & 31) * 4;
        *(float4*)&Ts[row][c4] = *(const float4*)(g_T + ((size_t)row * 64 + nj) * DDIM + d0 + c4);
    }
    __syncthreads();
    const float scale = 0.5f / 8192.0f;
    int d4 = (tid & 31) * 4;
    int nib = tid >> 5;
    float4 a8[8];
    #pragma unroll
    for (int g = 0; g < 8; g++) a8[g] = make_float4(0.f, 0.f, 0.f, 0.f);
    for (int pi = 0; pi < 64; pi++) {
        float4 t = *(const float4*)&Ts[pi][d4];
        #pragma unroll
        for (int g = 0; g < 8; g++) {
            float w = e[abs(pi - (nib * 8 + g))];
            a8[g].x += w * t.x; a8[g].y += w * t.y; a8[g].z += w * t.z; a8[g].w += w * t.w;
        }
    }
    #pragma unroll
    for (int g = 0; g < 8; g++) {
        int ni = nib * 8 + g;
        float cs = css[ni];
        size_t off = ((size_t)ni * 64 + nj) * DDIM + d0 + d4;
        float4 m = *(const float4*)(mw + off);
        float4 o;
        o.x = m.x + scale * (a8[g].x - cs * m.x);
        o.y = m.y + scale * (a8[g].y - cs * m.y);
        o.z = m.z + scale * (a8[g].z - cs * m.z);
        o.w = m.w + scale * (a8[g].w - cs * m.w);
        *(float4*)(out + off) = o;
    }
}

// ---------------- K4c: out-of-radius correction (corner nodes only) ----------------
__global__ __launch_bounds__(256) void k_corr(float* __restrict__ out) {
    int n = blockIdx.x;
    int ni = n >> 6, nj = n & 63;
    int u = max(ni, 63 - ni), v = max(nj, 63 - nj);
    if (u * u + v * v <= D2_MAX) return;
    __shared__ float e[64];
    int tid = threadIdx.x;
    float c2 = neg_inv_2r2();
    if (tid < 64) e[tid] = expf((float)(tid * tid) * c2);
    __syncthreads();
    int d4 = tid * 4;
    float4 acc = make_float4(0.f, 0.f, 0.f, 0.f);
    for (int pi = 0; pi < GRIDW; pi++) {
        int di = pi - ni;
        int t = isqrt_le(D2_MAX - di * di);
        float ei = e[abs(di)];
        for (int pj = 0; pj <= nj - t - 1; pj++) {
            float w = ei * e[nj - pj];
            float4 y = *(const float4*)(g_Y + ((size_t)pi * 64 + pj) * DDIM + d4);
            acc.x += w * y.x; acc.y += w * y.y; acc.z += w * y.z; acc.w += w * y.w;
        }
        for (int pj = nj + t + 1; pj < GRIDW; pj++) {
            float w = ei * e[pj - nj];
            float4 y = *(const float4*)(g_Y + ((size_t)pi * 64 + pj) * DDIM + d4);
            acc.x += w * y.x; acc.y += w * y.y; acc.z += w * y.z; acc.w += w * y.w;
        }
    }
    const float scale = 0.5f / 8192.0f;
    size_t off = (size_t)n * DDIM + d4;
    float4 o = *(float4*)(out + off);
    o.x -= scale * acc.x; o.y -= scale * acc.y; o.z -= scale * acc.z; o.w -= scale * acc.w;
    *(float4*)(out + off) = o;
}

// ---------------- launch ----------------
extern "C" void kernel_launch(void* const* d_in, const int* in_sizes, int n_in,
                              void* d_out, int out_size) {
    const float* x  = (const float*)d_in[0];
    const float* mw = (const float*)d_in[1];
    float* out = (float*)d_out;

    cudaFuncSetAttribute(k1a_score, cudaFuncAttributeMaxDynamicSharedMemorySize, K1_SMEM);

    k_init<<<NODES, 256>>>(mw);
    k_split<<<BSZ + NODES, 256>>>(x, mw);
    dim3 g1(NODES / 256, BSZ / 128);             // 16 x 64
    k1a_score<<<g1, 256, K1_SMEM>>>();
    k1b_refine<<<BSZ, 256>>>(x, mw);
    k_scatter<<<BSZ, 256>>>(x);
    k_colsum<<<GRIDW, 256>>>();
    dim3 gc(DDIM / 128, GRIDW);
    k_convA<<<gc, 256>>>();
    k_convB<<<gc, 256>>>(mw, out);
    k_corr<<<NODES, 256>>>(out);
}